// round 8
// baseline (speedup 1.0000x reference)
#include <cuda_runtime.h>
#include <cstdint>
#include <math.h>

// ----------------------------------------------------------------------------
// StackDevConv, factorized + dst-sorted edges + tf32 mma.
//   W1 = [Wa | Wb];  A[n] = x[n]@(Wa-Wb)^T + b1 ;  B[n] = x[n]@Wb^T   (fp32)
//   per edge: h = ReLU(A[dst]+B[src]);  msg = h @ W2^T + b2           (tf32 mma)
//   out[n] = segment_max(msg, dst) ; empty -> 0
// This round: (1) launch-order surgery so edge_kernel is launch #4 (the one
// ncu captures): zero_count folded into scan, scatter+init+pre fused into one
// block-range kernel. (2) W2 fragments pre-packed for LDS.64 (halves B-frag
// LDS). (3) scatter on 16-edge chains x 2 cols (fewer REDG).
// ----------------------------------------------------------------------------

#define DIMV    64
#define TPB     256
#define PADW    68
#define E_TILE  128
#define MAX_NODES 50000
#define MAX_EDGES 800000

#define SH 68    // sH / sMsg stride

__device__ float g_h1[MAX_NODES * DIMV];
__device__ float g_A [MAX_NODES * DIMV];
__device__ float g_B [MAX_NODES * DIMV];
__device__ int   g_count [MAX_NODES];
__device__ int   g_offset[MAX_NODES];
__device__ int   g_src_s[MAX_EDGES];
__device__ int   g_dst_s[MAX_EDGES];

#define PRE_SMEM_FLOATS (64*PADW*3 + 64)
#define PRE_SMEM_BYTES  (PRE_SMEM_FLOATS*4)

// edge smem (4B words): sW2p[64*32 uint2 = 4096w] + sB2[64] + sH[128*SH] + sDst[128]
#define EDGE_SMEM_WORDS (4096 + 64 + 128*SH + 128)
#define EDGE_SMEM_BYTES (EDGE_SMEM_WORDS*4)

__device__ __forceinline__ void atomic_max_float(float* addr, float value) {
    unsigned int ui = __float_as_uint(value);
    if ((int)ui >= 0) atomicMax((int*)addr, (int)ui);
    else              atomicMin((unsigned int*)addr, ui);
}

__device__ __forceinline__ unsigned int f2tf(float x) {
    unsigned int r;
    asm("cvt.rna.tf32.f32 %0, %1;" : "=r"(r) : "f"(x));
    return r;
}

__global__ void init_neg_inf_kernel(float* p, int n) {
    int i = blockIdx.x * blockDim.x + threadIdx.x;
    if (i < n) ((unsigned int*)p)[i] = 0xFF800000u;
}

__global__ void finalize_kernel(float* p, int n) {
    int i = blockIdx.x * blockDim.x + threadIdx.x;
    if (i < n) { float v = p[i]; if (!isfinite(v)) p[i] = 0.0f; }
}

// ---------------- counting sort by dst ----------------
__global__ void hist_kernel(const int* __restrict__ dst, int n_edges) {
    int i = blockIdx.x * blockDim.x + threadIdx.x;
    if (i < n_edges) atomicAdd(&g_count[dst[i]], 1);
}

// exclusive scan of g_count -> g_offset; re-zeros g_count for the next replay
// (first-ever run relies on zero-initialized __device__ BSS).
__global__ void scan_zero_kernel(int n_nodes) {
    __shared__ int partial[1024];
    const int tid = threadIdx.x;
    const int chunk = (n_nodes + 1023) / 1024;
    const int begin = tid * chunk;
    const int end   = min(begin + chunk, n_nodes);
    int s = 0;
    for (int i = begin; i < end; i++) s += g_count[i];
    partial[tid] = s;
    __syncthreads();
    for (int off = 1; off < 1024; off <<= 1) {
        int v = partial[tid];
        int add = (tid >= off) ? partial[tid - off] : 0;
        __syncthreads();
        partial[tid] = v + add;
        __syncthreads();
    }
    int base = (tid > 0) ? partial[tid - 1] : 0;
    for (int i = begin; i < end; i++) {
        g_offset[i] = base;
        base += g_count[i];
        g_count[i] = 0;
    }
}

// ---------------- per-node precompute body (fp32, exact) ----------------
__device__ __forceinline__
void pre_body(float* smem, int n0,
              const float* __restrict__ x,
              const float* __restrict__ W1, const float* __restrict__ b1,
              float* __restrict__ A, float* __restrict__ B,
              int n_nodes, int finite_fix, int tid)
{
    float* sWdT = smem;
    float* sWbT = sWdT + 64 * PADW;
    float* sB1  = sWbT + 64 * PADW;
    float* sXT  = sB1 + 64;

    for (int i = tid; i < 64 * 64; i += TPB) {
        int c = i >> 6, k = i & 63;
        float wa = W1[c * 128 + k];
        float wb = W1[c * 128 + 64 + k];
        sWdT[k * PADW + c] = wa - wb;
        sWbT[k * PADW + c] = wb;
    }
    if (tid < 64) sB1[tid] = b1[tid];

    {
        const int e = tid >> 2;
        const int q = tid & 3;
        const int node = n0 + e;
        const float4* xr = (const float4*)(x + (size_t)(node < n_nodes ? node : 0) * DIMV);
        #pragma unroll
        for (int v = 0; v < 4; v++) {
            const int c4 = q * 4 + v;
            float4 a = (node < n_nodes) ? xr[c4] : make_float4(0.f,0.f,0.f,0.f);
            if (finite_fix) {
                if (!isfinite(a.x)) a.x = 0.f;
                if (!isfinite(a.y)) a.y = 0.f;
                if (!isfinite(a.z)) a.z = 0.f;
                if (!isfinite(a.w)) a.w = 0.f;
            }
            const int c = c4 * 4;
            sXT[(c + 0) * PADW + e] = a.x;
            sXT[(c + 1) * PADW + e] = a.y;
            sXT[(c + 2) * PADW + e] = a.z;
            sXT[(c + 3) * PADW + e] = a.w;
        }
    }
    __syncthreads();

    const int ty = tid >> 4, tx = tid & 15;
    const int r = ty * 4, cc = tx * 4;

    float accA[4][4], accB[4][4];
    #pragma unroll
    for (int i = 0; i < 4; i++)
        #pragma unroll
        for (int j = 0; j < 4; j++) { accA[i][j] = sB1[cc + j]; accB[i][j] = 0.f; }

    #pragma unroll 2
    for (int k = 0; k < 64; k++) {
        const float4 xf = *(const float4*)&sXT[k * PADW + r];
        const float4 wd = *(const float4*)&sWdT[k * PADW + cc];
        const float4 wb = *(const float4*)&sWbT[k * PADW + cc];
        const float a0 = xf.x, a1 = xf.y, a2 = xf.z, a3 = xf.w;
        accA[0][0]+=a0*wd.x; accA[0][1]+=a0*wd.y; accA[0][2]+=a0*wd.z; accA[0][3]+=a0*wd.w;
        accA[1][0]+=a1*wd.x; accA[1][1]+=a1*wd.y; accA[1][2]+=a1*wd.z; accA[1][3]+=a1*wd.w;
        accA[2][0]+=a2*wd.x; accA[2][1]+=a2*wd.y; accA[2][2]+=a2*wd.z; accA[2][3]+=a2*wd.w;
        accA[3][0]+=a3*wd.x; accA[3][1]+=a3*wd.y; accA[3][2]+=a3*wd.z; accA[3][3]+=a3*wd.w;
        accB[0][0]+=a0*wb.x; accB[0][1]+=a0*wb.y; accB[0][2]+=a0*wb.z; accB[0][3]+=a0*wb.w;
        accB[1][0]+=a1*wb.x; accB[1][1]+=a1*wb.y; accB[1][2]+=a1*wb.z; accB[1][3]+=a1*wb.w;
        accB[2][0]+=a2*wb.x; accB[2][1]+=a2*wb.y; accB[2][2]+=a2*wb.z; accB[2][3]+=a2*wb.w;
        accB[3][0]+=a3*wb.x; accB[3][1]+=a3*wb.y; accB[3][2]+=a3*wb.z; accB[3][3]+=a3*wb.w;
    }

    #pragma unroll
    for (int i = 0; i < 4; i++) {
        const int node = n0 + r + i;
        if (node < n_nodes) {
            *(float4*)&A[(size_t)node * DIMV + cc] =
                make_float4(accA[i][0], accA[i][1], accA[i][2], accA[i][3]);
            *(float4*)&B[(size_t)node * DIMV + cc] =
                make_float4(accB[i][0], accB[i][1], accB[i][2], accB[i][3]);
        }
    }
}

__global__ __launch_bounds__(TPB, 3)
void pre_kernel(const float* __restrict__ x,
                const float* __restrict__ W1, const float* __restrict__ b1,
                float* __restrict__ A, float* __restrict__ B,
                int n_nodes, int finite_fix)
{
    extern __shared__ float smem[];
    pre_body(smem, blockIdx.x * 64, x, W1, b1, A, B, n_nodes, finite_fix, threadIdx.x);
}

// ---------------- fused scatter + init(h1) + pre(layer1) ----------------
// The three pieces are mutually independent; fusing them makes edge_kernel
// the 4th launch (the one ncu captures).
__global__ __launch_bounds__(TPB, 3)
void fused_spi_kernel(const int* __restrict__ src, const int* __restrict__ dst,
                      int n_edges,
                      const float* __restrict__ x,
                      const float* __restrict__ W1, const float* __restrict__ b1,
                      float* __restrict__ A, float* __restrict__ B, int n_nodes,
                      float* __restrict__ h1, int n_feat,
                      int nblk_scatter, int nblk_init)
{
    extern __shared__ float fsm[];
    const int b = blockIdx.x;
    if (b < nblk_scatter) {
        int i = b * TPB + threadIdx.x;
        if (i < n_edges) {
            int d = dst[i];
            int pos = atomicAdd(&g_offset[d], 1);
            g_src_s[pos] = src[i];
            g_dst_s[pos] = d;
        }
    } else if (b < nblk_scatter + nblk_init) {
        int i = (b - nblk_scatter) * TPB + threadIdx.x;
        if (i < n_feat) ((unsigned int*)h1)[i] = 0xFF800000u;
    } else {
        pre_body(fsm, (b - nblk_scatter - nblk_init) * 64,
                 x, W1, b1, A, B, n_nodes, 0, threadIdx.x);
    }
}

// ---------------- edge kernel: tf32 mma, packed W2 frags, chain-16 scatter ----
__global__ __launch_bounds__(TPB, 3)
void edge_kernel(const float* __restrict__ A, const float* __restrict__ B,
                 const float* __restrict__ W2, const float* __restrict__ b2,
                 float* __restrict__ out, int n_edges)
{
    extern __shared__ unsigned int usmem[];
    uint2*        sW2p = (uint2*)usmem;                // [64 ntks][32 lane] frag pairs
    float*        sB2  = (float*)(usmem + 4096);
    unsigned int* sH   = usmem + 4096 + 64;            // [e][k] tf32, stride SH
    float*        sMsg = (float*)sH;                   // ALIAS
    int*          sDst = (int*)(sH + 128 * SH);

    const int tid  = threadIdx.x;
    const int wid  = tid >> 5;
    const int lane = tid & 31;
    const int grp  = lane >> 2;
    const int qd   = lane & 3;

    // pack W2 fragments: sW2p[ntks][lane] = {tf32(W2[nt*8+grp][ks*8+qd]),
    //                                        tf32(W2[nt*8+grp][ks*8+qd+4])}
    for (int i = tid; i < 64 * 32; i += TPB) {
        const int l = i & 31, ntks = i >> 5;
        const int nt = ntks >> 3, ks = ntks & 7;
        const int row = nt * 8 + (l >> 2);
        const int c0  = ks * 8 + (l & 3);
        sW2p[i] = make_uint2(f2tf(W2[row * 64 + c0]), f2tf(W2[row * 64 + c0 + 4]));
    }
    if (tid < 64) sB2[tid] = b2[tid];
    __syncthreads();

    const int ty2 = tid >> 5, tx2 = tid & 31;          // scatter role
    const int r2 = ty2 * 16, cc2 = tx2 * 2;

    const int n_tiles = (n_edges + E_TILE - 1) / E_TILE;

    for (int tile = blockIdx.x; tile < n_tiles; tile += gridDim.x) {
        const int e0 = tile * E_TILE;

        // ---- gather + ReLU -> sH[e][k] (tf32), 2 threads/edge ----
        {
            const int e = tid >> 1;
            const int q = tid & 1;
            const int eg = e0 + e;
            const bool valid = (eg < n_edges);
            int s = 0, d = 0;
            if (valid) { s = g_src_s[eg]; d = g_dst_s[eg]; }
            if (q == 0) sDst[e] = valid ? d : -1;
            const float4* a4 = (const float4*)(A + (size_t)d * DIMV) + q * 8;
            const float4* b4 = (const float4*)(B + (size_t)s * DIMV) + q * 8;
            uint4* hp = (uint4*)&sH[e * SH] + q * 8;
            #pragma unroll
            for (int v = 0; v < 8; v++) {
                float4 a = valid ? a4[v] : make_float4(0.f,0.f,0.f,0.f);
                float4 b = valid ? b4[v] : make_float4(0.f,0.f,0.f,0.f);
                uint4 hv;
                hv.x = f2tf(fmaxf(a.x + b.x, 0.f));
                hv.y = f2tf(fmaxf(a.y + b.y, 0.f));
                hv.z = f2tf(fmaxf(a.z + b.z, 0.f));
                hv.w = f2tf(fmaxf(a.w + b.w, 0.f));
                hp[v] = hv;
            }
        }
        __syncthreads();   // sync1: sH/sDst ready

        // ---- load all A fragments, then fence before sMsg overwrites sH ----
        const int m0 = wid * 16;
        unsigned int af[8][4];
        #pragma unroll
        for (int ks = 0; ks < 8; ks++) {
            const int k0 = ks * 8;
            af[ks][0] = sH[(m0 + grp    ) * SH + k0 + qd    ];
            af[ks][1] = sH[(m0 + grp + 8) * SH + k0 + qd    ];
            af[ks][2] = sH[(m0 + grp    ) * SH + k0 + qd + 4];
            af[ks][3] = sH[(m0 + grp + 8) * SH + k0 + qd + 4];
        }
        __syncthreads();   // sync2: all af loaded; sH reusable as sMsg

        // ---- tf32 mma -> sMsg (aliases sH); B-frags via LDS.64 ----
        #pragma unroll
        for (int nt = 0; nt < 8; nt++) {
            float c0 = 0.f, c1 = 0.f, c2 = 0.f, c3 = 0.f;
            #pragma unroll
            for (int ks = 0; ks < 8; ks++) {
                const uint2 bp = sW2p[(nt * 8 + ks) * 32 + lane];
                asm volatile(
                    "mma.sync.aligned.m16n8k8.row.col.f32.tf32.tf32.f32 "
                    "{%0,%1,%2,%3}, {%4,%5,%6,%7}, {%8,%9}, {%0,%1,%2,%3};"
                    : "+f"(c0), "+f"(c1), "+f"(c2), "+f"(c3)
                    : "r"(af[ks][0]), "r"(af[ks][1]), "r"(af[ks][2]), "r"(af[ks][3]),
                      "r"(bp.x), "r"(bp.y));
            }
            const int col = nt * 8 + 2 * qd;
            const float bb0 = sB2[col], bb1 = sB2[col + 1];
            *(float2*)&sMsg[(m0 + grp    ) * SH + col] = make_float2(c0 + bb0, c1 + bb1);
            *(float2*)&sMsg[(m0 + grp + 8) * SH + col] = make_float2(c2 + bb0, c3 + bb1);
        }

        // dst chain for scatter (sDst stable until next gather)
        int rd[16];
        #pragma unroll
        for (int i4 = 0; i4 < 4; i4++)
            *(int4*)&rd[i4 * 4] = *(const int4*)&sDst[r2 + i4 * 4];
        __syncthreads();   // sync3: sMsg ready

        // ---- scatter: 16-edge chains x 2 cols, run-merged atomics ----
        {
            float2 cur = *(const float2*)&sMsg[r2 * SH + cc2];
            #pragma unroll
            for (int i = 0; i < 16; i++) {
                const int de = rd[i];
                const bool last = (i == 15) || (rd[i + 1] != de);
                if (!last) {
                    const float2 nx = *(const float2*)&sMsg[(r2 + i + 1) * SH + cc2];
                    cur.x = fmaxf(cur.x, nx.x);
                    cur.y = fmaxf(cur.y, nx.y);
                } else {
                    if (de >= 0) {
                        float* op = out + (size_t)de * DIMV + cc2;
                        atomic_max_float(op + 0, cur.x);
                        atomic_max_float(op + 1, cur.y);
                    }
                    if (i < 15)
                        cur = *(const float2*)&sMsg[(r2 + i + 1) * SH + cc2];
                }
            }
        }
        __syncthreads();   // sync4: scatter done; sMsg reusable as sH(t+1)
    }
}

extern "C" void kernel_launch(void* const* d_in, const int* in_sizes, int n_in,
                              void* d_out, int out_size)
{
    const float* x   = (const float*)d_in[0];
    const int*   ei  = (const int*)d_in[1];
    const float* W1a = (const float*)d_in[2];
    const float* b1a = (const float*)d_in[3];
    const float* W2a = (const float*)d_in[4];
    const float* b2a = (const float*)d_in[5];
    const float* W1b = (const float*)d_in[6];
    const float* b1b = (const float*)d_in[7];
    const float* W2b = (const float*)d_in[8];
    const float* b2b = (const float*)d_in[9];

    const int n_nodes = in_sizes[0] / DIMV;
    const int n_edges = in_sizes[1] / 2;
    const int* src = ei;
    const int* dst = ei + n_edges;

    float* out = (float*)d_out;
    float *h1, *Abuf, *Bbuf;
    cudaGetSymbolAddress((void**)&h1,   g_h1);
    cudaGetSymbolAddress((void**)&Abuf, g_A);
    cudaGetSymbolAddress((void**)&Bbuf, g_B);

    cudaFuncSetAttribute(pre_kernel,
                         cudaFuncAttributeMaxDynamicSharedMemorySize, PRE_SMEM_BYTES);
    cudaFuncSetAttribute(fused_spi_kernel,
                         cudaFuncAttributeMaxDynamicSharedMemorySize, PRE_SMEM_BYTES);
    cudaFuncSetAttribute(edge_kernel,
                         cudaFuncAttributeMaxDynamicSharedMemorySize, EDGE_SMEM_BYTES);

    const int n_feat = n_nodes * DIMV;
    const int init_blocks = (n_feat + TPB - 1) / TPB;
    const int pre_blocks  = (n_nodes + 63) / 64;
    const int edge_blocks = 148 * 3;
    const int eb = (n_edges + TPB - 1) / TPB;

    // #1 histogram (g_count zeroed by previous scan / initial BSS)
    hist_kernel<<<eb, TPB>>>(dst, n_edges);
    // #2 exclusive scan + re-zero counts
    scan_zero_kernel<<<1, 1024>>>(n_nodes);
    // #3 fused: scatter-sort + init(h1) + pre(layer1)  (mutually independent)
    fused_spi_kernel<<<eb + init_blocks + pre_blocks, TPB, PRE_SMEM_BYTES>>>(
        src, dst, n_edges, x, W1a, b1a, Abuf, Bbuf, n_nodes,
        h1, n_feat, eb, init_blocks);
    // #4 edge layer 1  <-- ncu captures this launch
    edge_kernel<<<edge_blocks, TPB, EDGE_SMEM_BYTES>>>(Abuf, Bbuf, W2a, b2a, h1, n_edges);

    // ---- layer 2 (h1 finalize fused via finite_fix) ----
    pre_kernel<<<pre_blocks, TPB, PRE_SMEM_BYTES>>>(h1, W1b, b1b, Abuf, Bbuf, n_nodes, 1);
    init_neg_inf_kernel<<<init_blocks, TPB>>>(out, n_feat);
    edge_kernel<<<edge_blocks, TPB, EDGE_SMEM_BYTES>>>(Abuf, Bbuf, W2b, b2b, out, n_edges);
    finalize_kernel<<<init_blocks, TPB>>>(out, n_feat);
}

// round 9
// speedup vs baseline: 1.0883x; 1.0883x over previous
#include <cuda_runtime.h>
#include <cstdint>
#include <math.h>

// ----------------------------------------------------------------------------
// StackDevConv, factorized + dst-sorted edges + tf32 mma (W2-in-registers).
//   W1 = [Wa | Wb];  A[n] = x[n]@(Wa-Wb)^T + b1 ;  B[n] = x[n]@Wb^T   (fp32)
//   per edge: h = ReLU(A[dst]+B[src]);  msg = h @ W2^T + b2           (tf32 mma)
//   out[n] = segment_max(msg, dst) ; empty -> 0
// R8 ncu: edge_kernel is L1TEX-bound (86.3%). Dominant smem stream was W2
// B-fragments re-read from smem by every warp every tile (512B/thr/tile,
// tile-invariant data!). Fix: warp owns a fixed 32-col slice; its 32 uint2
// W2 fragments are loaded ONCE into registers; ks-outer mma loop keeps the
// register count under the occ-2 cap. E_TILE=64, separate sMsg (stride 72,
// conflict-free), 3 barriers/tile, chain-16 x 1-col scatter.
// ----------------------------------------------------------------------------

#define DIMV    64
#define TPB     256
#define PADW    68
#define E_TILE  64
#define MAX_NODES 50000
#define MAX_EDGES 800000

#define SH  68   // sH stride (uint32)
#define SMS 72   // sMsg stride (float) -> conflict-free float2 stores

__device__ float g_h1[MAX_NODES * DIMV];
__device__ float g_A [MAX_NODES * DIMV];
__device__ float g_B [MAX_NODES * DIMV];
__device__ int   g_count [MAX_NODES];
__device__ int   g_offset[MAX_NODES];
__device__ int   g_src_s[MAX_EDGES];
__device__ int   g_dst_s[MAX_EDGES];

#define PRE_SMEM_FLOATS (64*PADW*3 + 64)
#define PRE_SMEM_BYTES  (PRE_SMEM_FLOATS*4)

// edge smem (4B words): sH[64*SH] + sMsg[64*SMS] + sDst[64]
#define EDGE_SMEM_WORDS (64*SH + 64*SMS + 64)
#define EDGE_SMEM_BYTES (EDGE_SMEM_WORDS*4)

__device__ __forceinline__ void atomic_max_float(float* addr, float value) {
    unsigned int ui = __float_as_uint(value);
    if ((int)ui >= 0) atomicMax((int*)addr, (int)ui);
    else              atomicMin((unsigned int*)addr, ui);
}

__device__ __forceinline__ unsigned int f2tf(float x) {
    unsigned int r;
    asm("cvt.rna.tf32.f32 %0, %1;" : "=r"(r) : "f"(x));
    return r;
}

__global__ void init_neg_inf_kernel(float* p, int n) {
    int i = blockIdx.x * blockDim.x + threadIdx.x;
    if (i < n) ((unsigned int*)p)[i] = 0xFF800000u;
}

__global__ void finalize_kernel(float* p, int n) {
    int i = blockIdx.x * blockDim.x + threadIdx.x;
    if (i < n) { float v = p[i]; if (!isfinite(v)) p[i] = 0.0f; }
}

// ---------------- counting sort by dst ----------------
__global__ void hist_kernel(const int* __restrict__ dst, int n_edges) {
    int i = blockIdx.x * blockDim.x + threadIdx.x;
    if (i < n_edges) atomicAdd(&g_count[dst[i]], 1);
}

// exclusive scan of g_count -> g_offset; re-zeros g_count for next replay.
__global__ void scan_zero_kernel(int n_nodes) {
    __shared__ int partial[1024];
    const int tid = threadIdx.x;
    const int chunk = (n_nodes + 1023) / 1024;
    const int begin = tid * chunk;
    const int end   = min(begin + chunk, n_nodes);
    int s = 0;
    for (int i = begin; i < end; i++) s += g_count[i];
    partial[tid] = s;
    __syncthreads();
    for (int off = 1; off < 1024; off <<= 1) {
        int v = partial[tid];
        int add = (tid >= off) ? partial[tid - off] : 0;
        __syncthreads();
        partial[tid] = v + add;
        __syncthreads();
    }
    int base = (tid > 0) ? partial[tid - 1] : 0;
    for (int i = begin; i < end; i++) {
        g_offset[i] = base;
        base += g_count[i];
        g_count[i] = 0;
    }
}

// ---------------- per-node precompute body (fp32, exact) ----------------
__device__ __forceinline__
void pre_body(float* smem, int n0,
              const float* __restrict__ x,
              const float* __restrict__ W1, const float* __restrict__ b1,
              float* __restrict__ A, float* __restrict__ B,
              int n_nodes, int finite_fix, int tid)
{
    float* sWdT = smem;
    float* sWbT = sWdT + 64 * PADW;
    float* sB1  = sWbT + 64 * PADW;
    float* sXT  = sB1 + 64;

    for (int i = tid; i < 64 * 64; i += TPB) {
        int c = i >> 6, k = i & 63;
        float wa = W1[c * 128 + k];
        float wb = W1[c * 128 + 64 + k];
        sWdT[k * PADW + c] = wa - wb;
        sWbT[k * PADW + c] = wb;
    }
    if (tid < 64) sB1[tid] = b1[tid];

    {
        const int e = tid >> 2;
        const int q = tid & 3;
        const int node = n0 + e;
        const float4* xr = (const float4*)(x + (size_t)(node < n_nodes ? node : 0) * DIMV);
        #pragma unroll
        for (int v = 0; v < 4; v++) {
            const int c4 = q * 4 + v;
            float4 a = (node < n_nodes) ? xr[c4] : make_float4(0.f,0.f,0.f,0.f);
            if (finite_fix) {
                if (!isfinite(a.x)) a.x = 0.f;
                if (!isfinite(a.y)) a.y = 0.f;
                if (!isfinite(a.z)) a.z = 0.f;
                if (!isfinite(a.w)) a.w = 0.f;
            }
            const int c = c4 * 4;
            sXT[(c + 0) * PADW + e] = a.x;
            sXT[(c + 1) * PADW + e] = a.y;
            sXT[(c + 2) * PADW + e] = a.z;
            sXT[(c + 3) * PADW + e] = a.w;
        }
    }
    __syncthreads();

    const int ty = tid >> 4, tx = tid & 15;
    const int r = ty * 4, cc = tx * 4;

    float accA[4][4], accB[4][4];
    #pragma unroll
    for (int i = 0; i < 4; i++)
        #pragma unroll
        for (int j = 0; j < 4; j++) { accA[i][j] = sB1[cc + j]; accB[i][j] = 0.f; }

    #pragma unroll 2
    for (int k = 0; k < 64; k++) {
        const float4 xf = *(const float4*)&sXT[k * PADW + r];
        const float4 wd = *(const float4*)&sWdT[k * PADW + cc];
        const float4 wb = *(const float4*)&sWbT[k * PADW + cc];
        const float a0 = xf.x, a1 = xf.y, a2 = xf.z, a3 = xf.w;
        accA[0][0]+=a0*wd.x; accA[0][1]+=a0*wd.y; accA[0][2]+=a0*wd.z; accA[0][3]+=a0*wd.w;
        accA[1][0]+=a1*wd.x; accA[1][1]+=a1*wd.y; accA[1][2]+=a1*wd.z; accA[1][3]+=a1*wd.w;
        accA[2][0]+=a2*wd.x; accA[2][1]+=a2*wd.y; accA[2][2]+=a2*wd.z; accA[2][3]+=a2*wd.w;
        accA[3][0]+=a3*wd.x; accA[3][1]+=a3*wd.y; accA[3][2]+=a3*wd.z; accA[3][3]+=a3*wd.w;
        accB[0][0]+=a0*wb.x; accB[0][1]+=a0*wb.y; accB[0][2]+=a0*wb.z; accB[0][3]+=a0*wb.w;
        accB[1][0]+=a1*wb.x; accB[1][1]+=a1*wb.y; accB[1][2]+=a1*wb.z; accB[1][3]+=a1*wb.w;
        accB[2][0]+=a2*wb.x; accB[2][1]+=a2*wb.y; accB[2][2]+=a2*wb.z; accB[2][3]+=a2*wb.w;
        accB[3][0]+=a3*wb.x; accB[3][1]+=a3*wb.y; accB[3][2]+=a3*wb.z; accB[3][3]+=a3*wb.w;
    }

    #pragma unroll
    for (int i = 0; i < 4; i++) {
        const int node = n0 + r + i;
        if (node < n_nodes) {
            *(float4*)&A[(size_t)node * DIMV + cc] =
                make_float4(accA[i][0], accA[i][1], accA[i][2], accA[i][3]);
            *(float4*)&B[(size_t)node * DIMV + cc] =
                make_float4(accB[i][0], accB[i][1], accB[i][2], accB[i][3]);
        }
    }
}

__global__ __launch_bounds__(TPB, 3)
void pre_kernel(const float* __restrict__ x,
                const float* __restrict__ W1, const float* __restrict__ b1,
                float* __restrict__ A, float* __restrict__ B,
                int n_nodes, int finite_fix)
{
    extern __shared__ float smem[];
    pre_body(smem, blockIdx.x * 64, x, W1, b1, A, B, n_nodes, finite_fix, threadIdx.x);
}

// ---------------- fused scatter + init(h1) + pre(layer1) ----------------
__global__ __launch_bounds__(TPB, 3)
void fused_spi_kernel(const int* __restrict__ src, const int* __restrict__ dst,
                      int n_edges,
                      const float* __restrict__ x,
                      const float* __restrict__ W1, const float* __restrict__ b1,
                      float* __restrict__ A, float* __restrict__ B, int n_nodes,
                      float* __restrict__ h1, int n_feat,
                      int nblk_scatter, int nblk_init)
{
    extern __shared__ float fsm[];
    const int b = blockIdx.x;
    if (b < nblk_scatter) {
        int i = b * TPB + threadIdx.x;
        if (i < n_edges) {
            int d = dst[i];
            int pos = atomicAdd(&g_offset[d], 1);
            g_src_s[pos] = src[i];
            g_dst_s[pos] = d;
        }
    } else if (b < nblk_scatter + nblk_init) {
        int i = (b - nblk_scatter) * TPB + threadIdx.x;
        if (i < n_feat) ((unsigned int*)h1)[i] = 0xFF800000u;
    } else {
        pre_body(fsm, (b - nblk_scatter - nblk_init) * 64,
                 x, W1, b1, A, B, n_nodes, 0, threadIdx.x);
    }
}

// ---------------- edge kernel: tf32 mma, W2 frags in registers ----------------
__global__ __launch_bounds__(TPB, 2)
void edge_kernel(const float* __restrict__ A, const float* __restrict__ B,
                 const float* __restrict__ W2, const float* __restrict__ b2,
                 float* __restrict__ out, int n_edges)
{
    extern __shared__ unsigned int usmem[];
    unsigned int* sH   = usmem;                          // [64][SH] tf32
    float*        sMsg = (float*)(usmem + 64 * SH);      // [64][SMS]
    int*          sDst = (int*)(usmem + 64 * SH + 64 * SMS);

    const int tid  = threadIdx.x;
    const int wid  = tid >> 5;
    const int lane = tid & 31;
    const int grp  = lane >> 2;
    const int qd   = lane & 3;

    const int m0  = (wid >> 1) * 16;   // warp's edge-group base (4 groups)
    const int n0w = (wid & 1) * 32;    // warp's column half

    // ---- W2 fragments -> registers, ONCE (tile-invariant) ----
    uint2 wB[4][8];
    #pragma unroll
    for (int nt = 0; nt < 4; nt++) {
        const int row = n0w + nt * 8 + grp;
        #pragma unroll
        for (int ks = 0; ks < 8; ks++) {
            const int c = ks * 8 + qd;
            wB[nt][ks] = make_uint2(f2tf(W2[row * 64 + c]),
                                    f2tf(W2[row * 64 + c + 4]));
        }
    }
    float bb0[4], bb1[4];
    #pragma unroll
    for (int nt = 0; nt < 4; nt++) {
        const int col = n0w + nt * 8 + 2 * qd;
        bb0[nt] = b2[col];
        bb1[nt] = b2[col + 1];
    }

    const int ch   = tid >> 6;     // scatter chain 0..3
    const int colS = tid & 63;     // scatter column
    const int r2   = ch * 16;

    const int n_tiles = (n_edges + E_TILE - 1) / E_TILE;

    for (int tile = blockIdx.x; tile < n_tiles; tile += gridDim.x) {
        const int e0 = tile * E_TILE;

        // ---- gather + ReLU -> sH[e][k] (tf32), 4 threads/edge ----
        {
            const int e = tid >> 2;
            const int q = tid & 3;
            const int eg = e0 + e;
            const bool valid = (eg < n_edges);
            int s = 0, d = 0;
            if (valid) { s = g_src_s[eg]; d = g_dst_s[eg]; }
            if (q == 0) sDst[e] = valid ? d : -1;
            const float4* a4 = (const float4*)(A + (size_t)d * DIMV) + q * 4;
            const float4* b4 = (const float4*)(B + (size_t)s * DIMV) + q * 4;
            uint4* hp = (uint4*)&sH[e * SH] + q * 4;
            #pragma unroll
            for (int v = 0; v < 4; v++) {
                float4 a = valid ? a4[v] : make_float4(0.f,0.f,0.f,0.f);
                float4 b = valid ? b4[v] : make_float4(0.f,0.f,0.f,0.f);
                uint4 hv;
                hv.x = f2tf(fmaxf(a.x + b.x, 0.f));
                hv.y = f2tf(fmaxf(a.y + b.y, 0.f));
                hv.z = f2tf(fmaxf(a.z + b.z, 0.f));
                hv.w = f2tf(fmaxf(a.w + b.w, 0.f));
                hp[v] = hv;
            }
        }
        __syncthreads();   // sync1: sH/sDst ready

        // ---- mma: ks outer (af transient), W2 frags from registers ----
        float acc[4][4];
        #pragma unroll
        for (int nt = 0; nt < 4; nt++)
            #pragma unroll
            for (int j = 0; j < 4; j++) acc[nt][j] = 0.f;

        #pragma unroll
        for (int ks = 0; ks < 8; ks++) {
            const int k0 = ks * 8;
            const unsigned int a0 = sH[(m0 + grp    ) * SH + k0 + qd    ];
            const unsigned int a1 = sH[(m0 + grp + 8) * SH + k0 + qd    ];
            const unsigned int a2 = sH[(m0 + grp    ) * SH + k0 + qd + 4];
            const unsigned int a3 = sH[(m0 + grp + 8) * SH + k0 + qd + 4];
            #pragma unroll
            for (int nt = 0; nt < 4; nt++) {
                asm volatile(
                    "mma.sync.aligned.m16n8k8.row.col.f32.tf32.tf32.f32 "
                    "{%0,%1,%2,%3}, {%4,%5,%6,%7}, {%8,%9}, {%0,%1,%2,%3};"
                    : "+f"(acc[nt][0]), "+f"(acc[nt][1]),
                      "+f"(acc[nt][2]), "+f"(acc[nt][3])
                    : "r"(a0), "r"(a1), "r"(a2), "r"(a3),
                      "r"(wB[nt][ks].x), "r"(wB[nt][ks].y));
            }
        }

        // ---- bias + write sMsg (stride 72: conflict-free STS.64) ----
        #pragma unroll
        for (int nt = 0; nt < 4; nt++) {
            const int c2 = n0w + nt * 8 + 2 * qd;
            *(float2*)&sMsg[(m0 + grp    ) * SMS + c2] =
                make_float2(acc[nt][0] + bb0[nt], acc[nt][1] + bb1[nt]);
            *(float2*)&sMsg[(m0 + grp + 8) * SMS + c2] =
                make_float2(acc[nt][2] + bb0[nt], acc[nt][3] + bb1[nt]);
        }

        // pre-read dst chain (sDst stable until next gather)
        int rd[16];
        #pragma unroll
        for (int i4 = 0; i4 < 4; i4++)
            *(int4*)&rd[i4 * 4] = *(const int4*)&sDst[r2 + i4 * 4];
        __syncthreads();   // sync2: sMsg ready, all sH reads done

        // ---- scatter: 16-edge chain x 1 col, run-merged atomics ----
        {
            float cur = sMsg[r2 * SMS + colS];
            #pragma unroll
            for (int i = 0; i < 16; i++) {
                const int de = rd[i];
                const bool last = (i == 15) || (rd[i + 1] != de);
                if (!last) {
                    cur = fmaxf(cur, sMsg[(r2 + i + 1) * SMS + colS]);
                } else {
                    if (de >= 0)
                        atomic_max_float(out + (size_t)de * DIMV + colS, cur);
                    if (i < 15)
                        cur = sMsg[(r2 + i + 1) * SMS + colS];
                }
            }
        }
        __syncthreads();   // sync3: scatter done; buffers reusable
    }
}

extern "C" void kernel_launch(void* const* d_in, const int* in_sizes, int n_in,
                              void* d_out, int out_size)
{
    const float* x   = (const float*)d_in[0];
    const int*   ei  = (const int*)d_in[1];
    const float* W1a = (const float*)d_in[2];
    const float* b1a = (const float*)d_in[3];
    const float* W2a = (const float*)d_in[4];
    const float* b2a = (const float*)d_in[5];
    const float* W1b = (const float*)d_in[6];
    const float* b1b = (const float*)d_in[7];
    const float* W2b = (const float*)d_in[8];
    const float* b2b = (const float*)d_in[9];

    const int n_nodes = in_sizes[0] / DIMV;
    const int n_edges = in_sizes[1] / 2;
    const int* src = ei;
    const int* dst = ei + n_edges;

    float* out = (float*)d_out;
    float *h1, *Abuf, *Bbuf;
    cudaGetSymbolAddress((void**)&h1,   g_h1);
    cudaGetSymbolAddress((void**)&Abuf, g_A);
    cudaGetSymbolAddress((void**)&Bbuf, g_B);

    cudaFuncSetAttribute(pre_kernel,
                         cudaFuncAttributeMaxDynamicSharedMemorySize, PRE_SMEM_BYTES);
    cudaFuncSetAttribute(fused_spi_kernel,
                         cudaFuncAttributeMaxDynamicSharedMemorySize, PRE_SMEM_BYTES);
    cudaFuncSetAttribute(edge_kernel,
                         cudaFuncAttributeMaxDynamicSharedMemorySize, EDGE_SMEM_BYTES);

    const int n_feat = n_nodes * DIMV;
    const int init_blocks = (n_feat + TPB - 1) / TPB;
    const int pre_blocks  = (n_nodes + 63) / 64;
    const int edge_blocks = 148 * 2;
    const int eb = (n_edges + TPB - 1) / TPB;

    // #1 histogram (g_count zeroed by previous scan / initial BSS)
    hist_kernel<<<eb, TPB>>>(dst, n_edges);
    // #2 exclusive scan + re-zero counts
    scan_zero_kernel<<<1, 1024>>>(n_nodes);
    // #3 fused: scatter-sort + init(h1) + pre(layer1)
    fused_spi_kernel<<<eb + init_blocks + pre_blocks, TPB, PRE_SMEM_BYTES>>>(
        src, dst, n_edges, x, W1a, b1a, Abuf, Bbuf, n_nodes,
        h1, n_feat, eb, init_blocks);
    // #4 edge layer 1  <-- ncu captures this launch
    edge_kernel<<<edge_blocks, TPB, EDGE_SMEM_BYTES>>>(Abuf, Bbuf, W2a, b2a, h1, n_edges);

    // ---- layer 2 (h1 finalize fused via finite_fix) ----
    pre_kernel<<<pre_blocks, TPB, PRE_SMEM_BYTES>>>(h1, W1b, b1b, Abuf, Bbuf, n_nodes, 1);
    init_neg_inf_kernel<<<init_blocks, TPB>>>(out, n_feat);
    edge_kernel<<<edge_blocks, TPB, EDGE_SMEM_BYTES>>>(Abuf, Bbuf, W2b, b2b, out, n_edges);
    finalize_kernel<<<init_blocks, TPB>>>(out, n_feat);
}

// round 11
// speedup vs baseline: 1.1086x; 1.0187x over previous
#include <cuda_runtime.h>
#include <cstdint>
#include <math.h>

// ----------------------------------------------------------------------------
// StackDevConv, factorized + dst-sorted edges + tf32 mma (W2-in-regs) +
// single-barrier software pipeline.
//   W1 = [Wa | Wb];  A[n] = x[n]@(Wa-Wb)^T + b1 ;  B[n] = x[n]@Wb^T   (fp32)
//   per edge: h = ReLU(A[dst]+B[src]);  msg = h @ W2^T + b2           (tf32 mma)
//   out[n] = segment_max(msg, dst) ; empty -> 0
// R9 ncu: edge_kernel stall-bound (L1 57%, issue 23%, occ 25%, no pipe
// saturated) -> cut barriers 3/tile -> 1/tile (double-buffered sH/sMsg,
// 4-deep sDst), prefetch B[src] (16 regs) under the mma, ldmatrix.x4 for
// A-fragments, contiguous tile blocks for A[dst] L1 locality.
// (R10 bench was an infra failure - container died before running; kernel
// re-audited: ldmatrix lane mapping and one-barrier race window verified.)
// ----------------------------------------------------------------------------

#define DIMV    64
#define TPB     256
#define PADW    68
#define E_TILE  64
#define MAX_NODES 50000
#define MAX_EDGES 800000

#define SH  68   // sH stride (uint32)
#define SMS 72   // sMsg stride (float)
#define SH_WORDS  (64*SH)    // 4352
#define SMS_WORDS (64*SMS)   // 4608

__device__ float g_h1[MAX_NODES * DIMV];
__device__ float g_A [MAX_NODES * DIMV];
__device__ float g_B [MAX_NODES * DIMV];
__device__ int   g_count [MAX_NODES];
__device__ int   g_offset[MAX_NODES];
__device__ int   g_src_s[MAX_EDGES];
__device__ int   g_dst_s[MAX_EDGES];

#define PRE_SMEM_FLOATS (64*PADW*3 + 64)
#define PRE_SMEM_BYTES  (PRE_SMEM_FLOATS*4)

// edge smem: sH[2] + sMsg[2] + sDst[4][64]
#define EDGE_SMEM_WORDS (2*SH_WORDS + 2*SMS_WORDS + 4*64)
#define EDGE_SMEM_BYTES (EDGE_SMEM_WORDS*4)

__device__ __forceinline__ void atomic_max_float(float* addr, float value) {
    unsigned int ui = __float_as_uint(value);
    if ((int)ui >= 0) atomicMax((int*)addr, (int)ui);
    else              atomicMin((unsigned int*)addr, ui);
}

__device__ __forceinline__ unsigned int f2tf(float x) {
    unsigned int r;
    asm("cvt.rna.tf32.f32 %0, %1;" : "=r"(r) : "f"(x));
    return r;
}

__device__ __forceinline__ void ldsm_x4(unsigned &r0, unsigned &r1,
                                        unsigned &r2, unsigned &r3,
                                        unsigned addr) {
    asm volatile("ldmatrix.sync.aligned.m8n8.x4.shared.b16 {%0,%1,%2,%3}, [%4];"
                 : "=r"(r0), "=r"(r1), "=r"(r2), "=r"(r3) : "r"(addr));
}

__global__ void init_neg_inf_kernel(float* p, int n) {
    int i = blockIdx.x * blockDim.x + threadIdx.x;
    if (i < n) ((unsigned int*)p)[i] = 0xFF800000u;
}

__global__ void finalize_kernel(float* p, int n) {
    int i = blockIdx.x * blockDim.x + threadIdx.x;
    if (i < n) { float v = p[i]; if (!isfinite(v)) p[i] = 0.0f; }
}

// ---------------- counting sort by dst ----------------
__global__ void hist_kernel(const int* __restrict__ dst, int n_edges) {
    int i = blockIdx.x * blockDim.x + threadIdx.x;
    if (i < n_edges) atomicAdd(&g_count[dst[i]], 1);
}

__global__ void scan_zero_kernel(int n_nodes) {
    __shared__ int partial[1024];
    const int tid = threadIdx.x;
    const int chunk = (n_nodes + 1023) / 1024;
    const int begin = tid * chunk;
    const int end   = min(begin + chunk, n_nodes);
    int s = 0;
    for (int i = begin; i < end; i++) s += g_count[i];
    partial[tid] = s;
    __syncthreads();
    for (int off = 1; off < 1024; off <<= 1) {
        int v = partial[tid];
        int add = (tid >= off) ? partial[tid - off] : 0;
        __syncthreads();
        partial[tid] = v + add;
        __syncthreads();
    }
    int base = (tid > 0) ? partial[tid - 1] : 0;
    for (int i = begin; i < end; i++) {
        g_offset[i] = base;
        base += g_count[i];
        g_count[i] = 0;
    }
}

// ---------------- per-node precompute body (fp32, exact) ----------------
__device__ __forceinline__
void pre_body(float* smem, int n0,
              const float* __restrict__ x,
              const float* __restrict__ W1, const float* __restrict__ b1,
              float* __restrict__ A, float* __restrict__ B,
              int n_nodes, int finite_fix, int tid)
{
    float* sWdT = smem;
    float* sWbT = sWdT + 64 * PADW;
    float* sB1  = sWbT + 64 * PADW;
    float* sXT  = sB1 + 64;

    for (int i = tid; i < 64 * 64; i += TPB) {
        int c = i >> 6, k = i & 63;
        float wa = W1[c * 128 + k];
        float wb = W1[c * 128 + 64 + k];
        sWdT[k * PADW + c] = wa - wb;
        sWbT[k * PADW + c] = wb;
    }
    if (tid < 64) sB1[tid] = b1[tid];

    {
        const int e = tid >> 2;
        const int q = tid & 3;
        const int node = n0 + e;
        const float4* xr = (const float4*)(x + (size_t)(node < n_nodes ? node : 0) * DIMV);
        #pragma unroll
        for (int v = 0; v < 4; v++) {
            const int c4 = q * 4 + v;
            float4 a = (node < n_nodes) ? xr[c4] : make_float4(0.f,0.f,0.f,0.f);
            if (finite_fix) {
                if (!isfinite(a.x)) a.x = 0.f;
                if (!isfinite(a.y)) a.y = 0.f;
                if (!isfinite(a.z)) a.z = 0.f;
                if (!isfinite(a.w)) a.w = 0.f;
            }
            const int c = c4 * 4;
            sXT[(c + 0) * PADW + e] = a.x;
            sXT[(c + 1) * PADW + e] = a.y;
            sXT[(c + 2) * PADW + e] = a.z;
            sXT[(c + 3) * PADW + e] = a.w;
        }
    }
    __syncthreads();

    const int ty = tid >> 4, tx = tid & 15;
    const int r = ty * 4, cc = tx * 4;

    float accA[4][4], accB[4][4];
    #pragma unroll
    for (int i = 0; i < 4; i++)
        #pragma unroll
        for (int j = 0; j < 4; j++) { accA[i][j] = sB1[cc + j]; accB[i][j] = 0.f; }

    #pragma unroll 2
    for (int k = 0; k < 64; k++) {
        const float4 xf = *(const float4*)&sXT[k * PADW + r];
        const float4 wd = *(const float4*)&sWdT[k * PADW + cc];
        const float4 wb = *(const float4*)&sWbT[k * PADW + cc];
        const float a0 = xf.x, a1 = xf.y, a2 = xf.z, a3 = xf.w;
        accA[0][0]+=a0*wd.x; accA[0][1]+=a0*wd.y; accA[0][2]+=a0*wd.z; accA[0][3]+=a0*wd.w;
        accA[1][0]+=a1*wd.x; accA[1][1]+=a1*wd.y; accA[1][2]+=a1*wd.z; accA[1][3]+=a1*wd.w;
        accA[2][0]+=a2*wd.x; accA[2][1]+=a2*wd.y; accA[2][2]+=a2*wd.z; accA[2][3]+=a2*wd.w;
        accA[3][0]+=a3*wd.x; accA[3][1]+=a3*wd.y; accA[3][2]+=a3*wd.z; accA[3][3]+=a3*wd.w;
        accB[0][0]+=a0*wb.x; accB[0][1]+=a0*wb.y; accB[0][2]+=a0*wb.z; accB[0][3]+=a0*wb.w;
        accB[1][0]+=a1*wb.x; accB[1][1]+=a1*wb.y; accB[1][2]+=a1*wb.z; accB[1][3]+=a1*wb.w;
        accB[2][0]+=a2*wb.x; accB[2][1]+=a2*wb.y; accB[2][2]+=a2*wb.z; accB[2][3]+=a2*wb.w;
        accB[3][0]+=a3*wb.x; accB[3][1]+=a3*wb.y; accB[3][2]+=a3*wb.z; accB[3][3]+=a3*wb.w;
    }

    #pragma unroll
    for (int i = 0; i < 4; i++) {
        const int node = n0 + r + i;
        if (node < n_nodes) {
            *(float4*)&A[(size_t)node * DIMV + cc] =
                make_float4(accA[i][0], accA[i][1], accA[i][2], accA[i][3]);
            *(float4*)&B[(size_t)node * DIMV + cc] =
                make_float4(accB[i][0], accB[i][1], accB[i][2], accB[i][3]);
        }
    }
}

__global__ __launch_bounds__(TPB, 3)
void pre_kernel(const float* __restrict__ x,
                const float* __restrict__ W1, const float* __restrict__ b1,
                float* __restrict__ A, float* __restrict__ B,
                int n_nodes, int finite_fix)
{
    extern __shared__ float smem[];
    pre_body(smem, blockIdx.x * 64, x, W1, b1, A, B, n_nodes, finite_fix, threadIdx.x);
}

// ---------------- fused scatter + init(h1) + pre(layer1) ----------------
__global__ __launch_bounds__(TPB, 3)
void fused_spi_kernel(const int* __restrict__ src, const int* __restrict__ dst,
                      int n_edges,
                      const float* __restrict__ x,
                      const float* __restrict__ W1, const float* __restrict__ b1,
                      float* __restrict__ A, float* __restrict__ B, int n_nodes,
                      float* __restrict__ h1, int n_feat,
                      int nblk_scatter, int nblk_init)
{
    extern __shared__ float fsm[];
    const int b = blockIdx.x;
    if (b < nblk_scatter) {
        int i = b * TPB + threadIdx.x;
        if (i < n_edges) {
            int d = dst[i];
            int pos = atomicAdd(&g_offset[d], 1);
            g_src_s[pos] = src[i];
            g_dst_s[pos] = d;
        }
    } else if (b < nblk_scatter + nblk_init) {
        int i = (b - nblk_scatter) * TPB + threadIdx.x;
        if (i < n_feat) ((unsigned int*)h1)[i] = 0xFF800000u;
    } else {
        pre_body(fsm, (b - nblk_scatter - nblk_init) * 64,
                 x, W1, b1, A, B, n_nodes, 0, threadIdx.x);
    }
}

// ---------------- edge kernel: pipelined, 1 barrier/tile ----------------
__global__ __launch_bounds__(TPB, 2)
void edge_kernel(const float* __restrict__ A, const float* __restrict__ B,
                 const float* __restrict__ W2, const float* __restrict__ b2,
                 float* __restrict__ out, int n_edges, int tiles_per_block)
{
    extern __shared__ unsigned int usmem[];
    unsigned int* sHb   = usmem;                              // 2 x [64][SH]
    float*        sMsgb = (float*)(usmem + 2 * SH_WORDS);     // 2 x [64][SMS]
    int*          sDstb = (int*)(usmem + 2 * SH_WORDS + 2 * SMS_WORDS); // 4 x [64]

    const int tid  = threadIdx.x;
    const int wid  = tid >> 5;
    const int lane = tid & 31;
    const int grp  = lane >> 2;
    const int qd   = lane & 3;

    const int m0  = (wid >> 1) * 16;   // warp's edge-group base
    const int n0w = (wid & 1) * 32;    // warp's column half

    // ---- W2 fragments -> registers, ONCE ----
    uint2 wB[4][8];
    #pragma unroll
    for (int nt = 0; nt < 4; nt++) {
        const int row = n0w + nt * 8 + grp;
        #pragma unroll
        for (int ks = 0; ks < 8; ks++) {
            const int c = ks * 8 + qd;
            wB[nt][ks] = make_uint2(f2tf(W2[row * 64 + c]),
                                    f2tf(W2[row * 64 + c + 4]));
        }
    }
    float bs0[4], bs1[4];
    #pragma unroll
    for (int nt = 0; nt < 4; nt++) {
        const int col = n0w + nt * 8 + 2 * qd;
        bs0[nt] = b2[col];
        bs1[nt] = b2[col + 1];
    }

    const int e = tid >> 2, q = tid & 3;        // gather role: 4 threads/edge
    const int colS = tid & 63, r2 = (tid >> 6) * 16;   // scatter role

    const int n_tiles = (n_edges + E_TILE - 1) / E_TILE;
    const int t0 = blockIdx.x * tiles_per_block;
    const int t1 = min(t0 + tiles_per_block, n_tiles);
    if (t0 >= t1) return;   // block-uniform

    // ldmatrix per-thread address offset (bytes, within a buffer)
    unsigned int sbase;
    asm("{ .reg .u64 t; cvta.to.shared.u64 t, %1; cvt.u32.u64 %0, t; }"
        : "=r"(sbase) : "l"((void*)usmem));
    const unsigned int lds_off =
        ((unsigned)((m0 + (lane & 15)) * SH + (lane >> 4) * 4)) * 4u;

    // ---- prologue: full gather of tile t0 -> sH buf0, sDst[t0&3] ----
    {
        const int eg = t0 * E_TILE + e;
        const bool valid = (eg < n_edges);
        int s = 0, d = -1;
        if (valid) { s = g_src_s[eg]; d = g_dst_s[eg]; }
        const float4* a4 = (const float4*)(A + (size_t)(valid ? d : 0) * DIMV) + q * 4;
        const float4* b4 = (const float4*)(B + (size_t)s * DIMV) + q * 4;
        uint4* hp = (uint4*)&sHb[e * SH] + q * 4;
        if (q == 0) sDstb[(t0 & 3) * 64 + e] = d;
        #pragma unroll
        for (int v = 0; v < 4; v++) {
            float4 a = valid ? a4[v] : make_float4(0.f,0.f,0.f,0.f);
            float4 b = valid ? b4[v] : make_float4(0.f,0.f,0.f,0.f);
            uint4 hv;
            hv.x = f2tf(fmaxf(a.x + b.x, 0.f));
            hv.y = f2tf(fmaxf(a.y + b.y, 0.f));
            hv.z = f2tf(fmaxf(a.z + b.z, 0.f));
            hv.w = f2tf(fmaxf(a.w + b.w, 0.f));
            hp[v] = hv;
        }
    }
    __syncthreads();

    int p = 0;
    for (int t = t0; t < t1; t++, p ^= 1) {
        // ---- 1. prefetch next tile's random B[src] (issues before mma) ----
        const int tn = t + 1;
        const int egN = tn * E_TILE + e;
        const bool validN = (tn < t1) && (egN < n_edges);
        int sN = 0, dN = -1;
        if (validN) { sN = g_src_s[egN]; dN = g_dst_s[egN]; }
        float4 bb[4];
        {
            const float4* b4 = (const float4*)(B + (size_t)sN * DIMV) + q * 4;
            #pragma unroll
            for (int v = 0; v < 4; v++)
                bb[v] = validN ? b4[v] : make_float4(0.f,0.f,0.f,0.f);
        }

        // ---- 2. mma from sH[p] via ldmatrix, W2 frags in regs ----
        float acc[4][4];
        #pragma unroll
        for (int nt = 0; nt < 4; nt++)
            #pragma unroll
            for (int j = 0; j < 4; j++) acc[nt][j] = 0.f;

        const unsigned int abase = sbase + (unsigned)p * (SH_WORDS * 4u) + lds_off;
        #pragma unroll
        for (int ks = 0; ks < 8; ks++) {
            unsigned int a0, a1, a2, a3;
            ldsm_x4(a0, a1, a2, a3, abase + ks * 32u);
            #pragma unroll
            for (int nt = 0; nt < 4; nt++) {
                asm volatile(
                    "mma.sync.aligned.m16n8k8.row.col.f32.tf32.tf32.f32 "
                    "{%0,%1,%2,%3}, {%4,%5,%6,%7}, {%8,%9}, {%0,%1,%2,%3};"
                    : "+f"(acc[nt][0]), "+f"(acc[nt][1]),
                      "+f"(acc[nt][2]), "+f"(acc[nt][3])
                    : "r"(a0), "r"(a1), "r"(a2), "r"(a3),
                      "r"(wB[nt][ks].x), "r"(wB[nt][ks].y));
            }
        }

        // ---- 3. finish next-tile gather: A row (cache-hot) + fuse + STS ----
        {
            const float4* a4 = (const float4*)(A + (size_t)(validN ? dN : 0) * DIMV) + q * 4;
            uint4* hp = (uint4*)&sHb[(p ^ 1) * SH_WORDS + e * SH] + q * 4;
            if (q == 0) sDstb[(tn & 3) * 64 + e] = dN;
            #pragma unroll
            for (int v = 0; v < 4; v++) {
                float4 a = validN ? a4[v] : make_float4(0.f,0.f,0.f,0.f);
                uint4 hv;
                hv.x = f2tf(fmaxf(a.x + bb[v].x, 0.f));
                hv.y = f2tf(fmaxf(a.y + bb[v].y, 0.f));
                hv.z = f2tf(fmaxf(a.z + bb[v].z, 0.f));
                hv.w = f2tf(fmaxf(a.w + bb[v].w, 0.f));
                hp[v] = hv;
            }
        }

        // ---- 4. bias + write sMsg[p] ----
        float* msg = sMsgb + p * SMS_WORDS;
        #pragma unroll
        for (int nt = 0; nt < 4; nt++) {
            const int c2 = n0w + nt * 8 + 2 * qd;
            *(float2*)&msg[(m0 + grp    ) * SMS + c2] =
                make_float2(acc[nt][0] + bs0[nt], acc[nt][1] + bs1[nt]);
            *(float2*)&msg[(m0 + grp + 8) * SMS + c2] =
                make_float2(acc[nt][2] + bs0[nt], acc[nt][3] + bs1[nt]);
        }
        __syncthreads();   // the ONE barrier: sMsg[p], sH[p^1], sDst ready

        // ---- 5. scatter from sMsg[p] / sDst[t&3] ----
        {
            const int* sd = sDstb + (t & 3) * 64;
            int rd[16];
            #pragma unroll
            for (int i4 = 0; i4 < 4; i4++)
                *(int4*)&rd[i4 * 4] = *(const int4*)&sd[r2 + i4 * 4];
            float cur = msg[r2 * SMS + colS];
            #pragma unroll
            for (int i = 0; i < 16; i++) {
                const int de = rd[i];
                const bool last = (i == 15) || (rd[i + 1] != de);
                if (!last) {
                    cur = fmaxf(cur, msg[(r2 + i + 1) * SMS + colS]);
                } else {
                    if (de >= 0)
                        atomic_max_float(out + (size_t)de * DIMV + colS, cur);
                    if (i < 15)
                        cur = msg[(r2 + i + 1) * SMS + colS];
                }
            }
        }
        // no trailing barrier: next iter writes sMsg[p^1]/sH[p]/sDst[(t+2)&3],
        // none of which are read in this window (verified buffer rotation).
    }
}

extern "C" void kernel_launch(void* const* d_in, const int* in_sizes, int n_in,
                              void* d_out, int out_size)
{
    const float* x   = (const float*)d_in[0];
    const int*   ei  = (const int*)d_in[1];
    const float* W1a = (const float*)d_in[2];
    const float* b1a = (const float*)d_in[3];
    const float* W2a = (const float*)d_in[4];
    const float* b2a = (const float*)d_in[5];
    const float* W1b = (const float*)d_in[6];
    const float* b1b = (const float*)d_in[7];
    const float* W2b = (const float*)d_in[8];
    const float* b2b = (const float*)d_in[9];

    const int n_nodes = in_sizes[0] / DIMV;
    const int n_edges = in_sizes[1] / 2;
    const int* src = ei;
    const int* dst = ei + n_edges;

    float* out = (float*)d_out;
    float *h1, *Abuf, *Bbuf;
    cudaGetSymbolAddress((void**)&h1,   g_h1);
    cudaGetSymbolAddress((void**)&Abuf, g_A);
    cudaGetSymbolAddress((void**)&Bbuf, g_B);

    cudaFuncSetAttribute(pre_kernel,
                         cudaFuncAttributeMaxDynamicSharedMemorySize, PRE_SMEM_BYTES);
    cudaFuncSetAttribute(fused_spi_kernel,
                         cudaFuncAttributeMaxDynamicSharedMemorySize, PRE_SMEM_BYTES);
    cudaFuncSetAttribute(edge_kernel,
                         cudaFuncAttributeMaxDynamicSharedMemorySize, EDGE_SMEM_BYTES);

    const int n_feat = n_nodes * DIMV;
    const int init_blocks = (n_feat + TPB - 1) / TPB;
    const int pre_blocks  = (n_nodes + 63) / 64;
    const int edge_blocks = 148 * 2;
    const int eb = (n_edges + TPB - 1) / TPB;

    const int n_tiles = (n_edges + E_TILE - 1) / E_TILE;
    const int tiles_per_block = (n_tiles + edge_blocks - 1) / edge_blocks;

    // #1 histogram (g_count zeroed by previous scan / initial BSS)
    hist_kernel<<<eb, TPB>>>(dst, n_edges);
    // #2 exclusive scan + re-zero counts
    scan_zero_kernel<<<1, 1024>>>(n_nodes);
    // #3 fused: scatter-sort + init(h1) + pre(layer1)
    fused_spi_kernel<<<eb + init_blocks + pre_blocks, TPB, PRE_SMEM_BYTES>>>(
        src, dst, n_edges, x, W1a, b1a, Abuf, Bbuf, n_nodes,
        h1, n_feat, eb, init_blocks);
    // #4 edge layer 1  <-- ncu captures this launch
    edge_kernel<<<edge_blocks, TPB, EDGE_SMEM_BYTES>>>(Abuf, Bbuf, W2a, b2a,
                                                       h1, n_edges, tiles_per_block);

    // ---- layer 2 (h1 finalize fused via finite_fix) ----
    pre_kernel<<<pre_blocks, TPB, PRE_SMEM_BYTES>>>(h1, W1b, b1b, Abuf, Bbuf, n_nodes, 1);
    init_neg_inf_kernel<<<init_blocks, TPB>>>(out, n_feat);
    edge_kernel<<<edge_blocks, TPB, EDGE_SMEM_BYTES>>>(Abuf, Bbuf, W2b, b2b,
                                                       out, n_edges, tiles_per_block);
    finalize_kernel<<<init_blocks, TPB>>>(out, n_feat);
}

// round 12
// speedup vs baseline: 1.2241x; 1.1042x over previous
#include <cuda_runtime.h>
#include <cuda_fp16.h>
#include <cstdint>
#include <math.h>

// ----------------------------------------------------------------------------
// StackDevConv, factorized + dst-sorted edges + f16 mma (W2-in-regs) +
// single-barrier software pipeline.
//   W1 = [Wa | Wb];  A[n] = x[n]@(Wa-Wb)^T + b1 ;  B[n] = x[n]@Wb^T   (fp32)
//   per edge: h = ReLU(A[dst]+B[src]) (fp32, rounded to f16);
//             msg = h @ W2^T + b2  (mma.m16n8k16.f16, fp32 accum)
//   out[n] = segment_max(msg, dst) ; empty -> 0
// R11 ncu: edge_kernel issue/latency-bound (~200 instr/thread/tile, issue 26%).
// f16 (same 11-bit mantissa as tf32) halves mma count, W2 regs, sH bytes,
// cvt count -> ~160 instr/thread/tile and fewer L1 wavefronts.
// ----------------------------------------------------------------------------

#define DIMV    64
#define TPB     256
#define PADW    68
#define E_TILE  64
#define MAX_NODES 50000
#define MAX_EDGES 800000

#define SHH 36                    // sH stride in 32-bit words (64 halves + pad)
#define SMS 72                    // sMsg stride (float)
#define SHH_WORDS (64*SHH)        // 2304
#define SMS_WORDS (64*SMS)        // 4608

__device__ float g_h1[MAX_NODES * DIMV];
__device__ float g_A [MAX_NODES * DIMV];
__device__ float g_B [MAX_NODES * DIMV];
__device__ int   g_count [MAX_NODES];
__device__ int   g_offset[MAX_NODES];
__device__ int   g_src_s[MAX_EDGES];
__device__ int   g_dst_s[MAX_EDGES];

#define PRE_SMEM_FLOATS (64*PADW*3 + 64)
#define PRE_SMEM_BYTES  (PRE_SMEM_FLOATS*4)

// edge smem: sH[2 x 2304] + sMsg[2 x 4608] + sDst[4][64]
#define EDGE_SMEM_WORDS (2*SHH_WORDS + 2*SMS_WORDS + 4*64)
#define EDGE_SMEM_BYTES (EDGE_SMEM_WORDS*4)

__device__ __forceinline__ void atomic_max_float(float* addr, float value) {
    unsigned int ui = __float_as_uint(value);
    if ((int)ui >= 0) atomicMax((int*)addr, (int)ui);
    else              atomicMin((unsigned int*)addr, ui);
}

// pack 2 floats -> f16x2 word (lo -> low half, matches memory col order)
__device__ __forceinline__ unsigned int pkh2(float lo, float hi) {
    __half2 h = __float22half2_rn(make_float2(lo, hi));
    return *reinterpret_cast<unsigned int*>(&h);
}

__device__ __forceinline__ void ldsm_x4(unsigned &r0, unsigned &r1,
                                        unsigned &r2, unsigned &r3,
                                        unsigned addr) {
    asm volatile("ldmatrix.sync.aligned.m8n8.x4.shared.b16 {%0,%1,%2,%3}, [%4];"
                 : "=r"(r0), "=r"(r1), "=r"(r2), "=r"(r3) : "r"(addr));
}

__global__ void init_neg_inf_kernel(float* p, int n) {
    int i = blockIdx.x * blockDim.x + threadIdx.x;
    if (i < n) ((unsigned int*)p)[i] = 0xFF800000u;
}

__global__ void finalize_kernel(float* p, int n) {
    int i = blockIdx.x * blockDim.x + threadIdx.x;
    if (i < n) { float v = p[i]; if (!isfinite(v)) p[i] = 0.0f; }
}

// ---------------- counting sort by dst ----------------
__global__ void hist_kernel(const int* __restrict__ dst, int n_edges) {
    int i = blockIdx.x * blockDim.x + threadIdx.x;
    if (i < n_edges) atomicAdd(&g_count[dst[i]], 1);
}

__global__ void scan_zero_kernel(int n_nodes) {
    __shared__ int partial[1024];
    const int tid = threadIdx.x;
    const int chunk = (n_nodes + 1023) / 1024;
    const int begin = tid * chunk;
    const int end   = min(begin + chunk, n_nodes);
    int s = 0;
    for (int i = begin; i < end; i++) s += g_count[i];
    partial[tid] = s;
    __syncthreads();
    for (int off = 1; off < 1024; off <<= 1) {
        int v = partial[tid];
        int add = (tid >= off) ? partial[tid - off] : 0;
        __syncthreads();
        partial[tid] = v + add;
        __syncthreads();
    }
    int base = (tid > 0) ? partial[tid - 1] : 0;
    for (int i = begin; i < end; i++) {
        g_offset[i] = base;
        base += g_count[i];
        g_count[i] = 0;
    }
}

// ---------------- per-node precompute body (fp32, exact) ----------------
__device__ __forceinline__
void pre_body(float* smem, int n0,
              const float* __restrict__ x,
              const float* __restrict__ W1, const float* __restrict__ b1,
              float* __restrict__ A, float* __restrict__ B,
              int n_nodes, int finite_fix, int tid)
{
    float* sWdT = smem;
    float* sWbT = sWdT + 64 * PADW;
    float* sB1  = sWbT + 64 * PADW;
    float* sXT  = sB1 + 64;

    for (int i = tid; i < 64 * 64; i += TPB) {
        int c = i >> 6, k = i & 63;
        float wa = W1[c * 128 + k];
        float wb = W1[c * 128 + 64 + k];
        sWdT[k * PADW + c] = wa - wb;
        sWbT[k * PADW + c] = wb;
    }
    if (tid < 64) sB1[tid] = b1[tid];

    {
        const int e = tid >> 2;
        const int q = tid & 3;
        const int node = n0 + e;
        const float4* xr = (const float4*)(x + (size_t)(node < n_nodes ? node : 0) * DIMV);
        #pragma unroll
        for (int v = 0; v < 4; v++) {
            const int c4 = q * 4 + v;
            float4 a = (node < n_nodes) ? xr[c4] : make_float4(0.f,0.f,0.f,0.f);
            if (finite_fix) {
                if (!isfinite(a.x)) a.x = 0.f;
                if (!isfinite(a.y)) a.y = 0.f;
                if (!isfinite(a.z)) a.z = 0.f;
                if (!isfinite(a.w)) a.w = 0.f;
            }
            const int c = c4 * 4;
            sXT[(c + 0) * PADW + e] = a.x;
            sXT[(c + 1) * PADW + e] = a.y;
            sXT[(c + 2) * PADW + e] = a.z;
            sXT[(c + 3) * PADW + e] = a.w;
        }
    }
    __syncthreads();

    const int ty = tid >> 4, tx = tid & 15;
    const int r = ty * 4, cc = tx * 4;

    float accA[4][4], accB[4][4];
    #pragma unroll
    for (int i = 0; i < 4; i++)
        #pragma unroll
        for (int j = 0; j < 4; j++) { accA[i][j] = sB1[cc + j]; accB[i][j] = 0.f; }

    #pragma unroll 2
    for (int k = 0; k < 64; k++) {
        const float4 xf = *(const float4*)&sXT[k * PADW + r];
        const float4 wd = *(const float4*)&sWdT[k * PADW + cc];
        const float4 wb = *(const float4*)&sWbT[k * PADW + cc];
        const float a0 = xf.x, a1 = xf.y, a2 = xf.z, a3 = xf.w;
        accA[0][0]+=a0*wd.x; accA[0][1]+=a0*wd.y; accA[0][2]+=a0*wd.z; accA[0][3]+=a0*wd.w;
        accA[1][0]+=a1*wd.x; accA[1][1]+=a1*wd.y; accA[1][2]+=a1*wd.z; accA[1][3]+=a1*wd.w;
        accA[2][0]+=a2*wd.x; accA[2][1]+=a2*wd.y; accA[2][2]+=a2*wd.z; accA[2][3]+=a2*wd.w;
        accA[3][0]+=a3*wd.x; accA[3][1]+=a3*wd.y; accA[3][2]+=a3*wd.z; accA[3][3]+=a3*wd.w;
        accB[0][0]+=a0*wb.x; accB[0][1]+=a0*wb.y; accB[0][2]+=a0*wb.z; accB[0][3]+=a0*wb.w;
        accB[1][0]+=a1*wb.x; accB[1][1]+=a1*wb.y; accB[1][2]+=a1*wb.z; accB[1][3]+=a1*wb.w;
        accB[2][0]+=a2*wb.x; accB[2][1]+=a2*wb.y; accB[2][2]+=a2*wb.z; accB[2][3]+=a2*wb.w;
        accB[3][0]+=a3*wb.x; accB[3][1]+=a3*wb.y; accB[3][2]+=a3*wb.z; accB[3][3]+=a3*wb.w;
    }

    #pragma unroll
    for (int i = 0; i < 4; i++) {
        const int node = n0 + r + i;
        if (node < n_nodes) {
            *(float4*)&A[(size_t)node * DIMV + cc] =
                make_float4(accA[i][0], accA[i][1], accA[i][2], accA[i][3]);
            *(float4*)&B[(size_t)node * DIMV + cc] =
                make_float4(accB[i][0], accB[i][1], accB[i][2], accB[i][3]);
        }
    }
}

__global__ __launch_bounds__(TPB, 3)
void pre_kernel(const float* __restrict__ x,
                const float* __restrict__ W1, const float* __restrict__ b1,
                float* __restrict__ A, float* __restrict__ B,
                int n_nodes, int finite_fix)
{
    extern __shared__ float smem[];
    pre_body(smem, blockIdx.x * 64, x, W1, b1, A, B, n_nodes, finite_fix, threadIdx.x);
}

// ---------------- fused scatter + init(h1) + pre(layer1) ----------------
__global__ __launch_bounds__(TPB, 3)
void fused_spi_kernel(const int* __restrict__ src, const int* __restrict__ dst,
                      int n_edges,
                      const float* __restrict__ x,
                      const float* __restrict__ W1, const float* __restrict__ b1,
                      float* __restrict__ A, float* __restrict__ B, int n_nodes,
                      float* __restrict__ h1, int n_feat,
                      int nblk_scatter, int nblk_init)
{
    extern __shared__ float fsm[];
    const int b = blockIdx.x;
    if (b < nblk_scatter) {
        int i = b * TPB + threadIdx.x;
        if (i < n_edges) {
            int d = dst[i];
            int pos = atomicAdd(&g_offset[d], 1);
            g_src_s[pos] = src[i];
            g_dst_s[pos] = d;
        }
    } else if (b < nblk_scatter + nblk_init) {
        int i = (b - nblk_scatter) * TPB + threadIdx.x;
        if (i < n_feat) ((unsigned int*)h1)[i] = 0xFF800000u;
    } else {
        pre_body(fsm, (b - nblk_scatter - nblk_init) * 64,
                 x, W1, b1, A, B, n_nodes, 0, threadIdx.x);
    }
}

// ---------------- edge kernel: f16 mma pipeline, 1 barrier/tile ----------------
__global__ __launch_bounds__(TPB, 2)
void edge_kernel(const float* __restrict__ A, const float* __restrict__ B,
                 const float* __restrict__ W2, const float* __restrict__ b2,
                 float* __restrict__ out, int n_edges, int tiles_per_block)
{
    extern __shared__ unsigned int usmem[];
    unsigned int* sHb   = usmem;                               // 2 x [64][SHH]
    float*        sMsgb = (float*)(usmem + 2 * SHH_WORDS);     // 2 x [64][SMS]
    int*          sDstb = (int*)(usmem + 2 * SHH_WORDS + 2 * SMS_WORDS); // 4 x [64]

    const int tid  = threadIdx.x;
    const int wid  = tid >> 5;
    const int lane = tid & 31;
    const int grp  = lane >> 2;
    const int qd   = lane & 3;

    const int m0  = (wid >> 1) * 16;   // warp's edge-group base
    const int n0w = (wid & 1) * 32;    // warp's column half

    // ---- W2 f16 fragments -> registers, ONCE (m16n8k16 B layout) ----
    // wB[nt][ks].x = {B[k0+2qd][n], B[k0+2qd+1][n]}  (B[k][n] = W2[n][k])
    // wB[nt][ks].y = {B[k0+8+2qd][n], B[k0+9+2qd][n]},  k0 = ks*16
    uint2 wB[4][4];
    #pragma unroll
    for (int nt = 0; nt < 4; nt++) {
        const int row = n0w + nt * 8 + grp;
        #pragma unroll
        for (int ks = 0; ks < 4; ks++) {
            const int k0 = ks * 16 + 2 * qd;
            wB[nt][ks] = make_uint2(
                pkh2(W2[row * 64 + k0    ], W2[row * 64 + k0 + 1]),
                pkh2(W2[row * 64 + k0 + 8], W2[row * 64 + k0 + 9]));
        }
    }
    float bs0[4], bs1[4];
    #pragma unroll
    for (int nt = 0; nt < 4; nt++) {
        const int col = n0w + nt * 8 + 2 * qd;
        bs0[nt] = b2[col];
        bs1[nt] = b2[col + 1];
    }

    const int e = tid >> 2, q = tid & 3;        // gather role: 4 threads/edge
    const int colS = tid & 63, r2 = (tid >> 6) * 16;   // scatter role

    const int n_tiles = (n_edges + E_TILE - 1) / E_TILE;
    const int t0 = blockIdx.x * tiles_per_block;
    const int t1 = min(t0 + tiles_per_block, n_tiles);
    if (t0 >= t1) return;   // block-uniform

    unsigned int sbase;
    asm("{ .reg .u64 t; cvta.to.shared.u64 t, %1; cvt.u32.u64 %0, t; }"
        : "=r"(sbase) : "l"((void*)usmem));
    // ldmatrix.x4 b16: lanes 0-7 rows m0+0..7, 8-15 rows m0+8..15 (halves 0-7);
    // lanes 16-31 same rows, +16B (halves 8-15). Row stride = SHH*4 = 144B.
    const unsigned int lds_off =
        ((unsigned)((m0 + (lane & 15)) * SHH + (lane >> 4) * 4)) * 4u;

    // gather h write: bytes e*144 + q*32 (two uint4 = 16 f16 cols per thread)
    // conflict-free: word idx = e*36 + q*8 mod 32 distinct per 8-lane phase.

    // ---- prologue: full gather of tile t0 -> sH buf0, sDst[t0&3] ----
    {
        const int eg = t0 * E_TILE + e;
        const bool valid = (eg < n_edges);
        int s = 0, d = -1;
        if (valid) { s = g_src_s[eg]; d = g_dst_s[eg]; }
        const float4* a4 = (const float4*)(A + (size_t)(valid ? d : 0) * DIMV) + q * 4;
        const float4* b4 = (const float4*)(B + (size_t)s * DIMV) + q * 4;
        uint4* hp = (uint4*)((char*)sHb + e * (SHH * 4) + q * 32);
        if (q == 0) sDstb[(t0 & 3) * 64 + e] = d;
        #pragma unroll
        for (int v = 0; v < 2; v++) {
            float4 x0 = valid ? a4[2*v  ] : make_float4(0.f,0.f,0.f,0.f);
            float4 x1 = valid ? a4[2*v+1] : make_float4(0.f,0.f,0.f,0.f);
            float4 y0 = valid ? b4[2*v  ] : make_float4(0.f,0.f,0.f,0.f);
            float4 y1 = valid ? b4[2*v+1] : make_float4(0.f,0.f,0.f,0.f);
            uint4 hv;
            hv.x = pkh2(fmaxf(x0.x + y0.x, 0.f), fmaxf(x0.y + y0.y, 0.f));
            hv.y = pkh2(fmaxf(x0.z + y0.z, 0.f), fmaxf(x0.w + y0.w, 0.f));
            hv.z = pkh2(fmaxf(x1.x + y1.x, 0.f), fmaxf(x1.y + y1.y, 0.f));
            hv.w = pkh2(fmaxf(x1.z + y1.z, 0.f), fmaxf(x1.w + y1.w, 0.f));
            hp[v] = hv;
        }
    }
    __syncthreads();

    int p = 0;
    for (int t = t0; t < t1; t++, p ^= 1) {
        // ---- 1. prefetch next tile's random B[src] (issues before mma) ----
        const int tn = t + 1;
        const int egN = tn * E_TILE + e;
        const bool validN = (tn < t1) && (egN < n_edges);
        int sN = 0, dN = -1;
        if (validN) { sN = g_src_s[egN]; dN = g_dst_s[egN]; }
        float4 bb[4];
        {
            const float4* b4 = (const float4*)(B + (size_t)sN * DIMV) + q * 4;
            #pragma unroll
            for (int v = 0; v < 4; v++)
                bb[v] = validN ? b4[v] : make_float4(0.f,0.f,0.f,0.f);
        }

        // ---- 2. f16 mma from sH[p] via ldmatrix, W2 frags in regs ----
        float acc[4][4];
        #pragma unroll
        for (int nt = 0; nt < 4; nt++)
            #pragma unroll
            for (int j = 0; j < 4; j++) acc[nt][j] = 0.f;

        const unsigned int abase = sbase + (unsigned)p * (SHH_WORDS * 4u) + lds_off;
        #pragma unroll
        for (int ks = 0; ks < 4; ks++) {
            unsigned int a0, a1, a2, a3;
            ldsm_x4(a0, a1, a2, a3, abase + ks * 32u);   // 16 halves per k-step
            #pragma unroll
            for (int nt = 0; nt < 4; nt++) {
                asm volatile(
                    "mma.sync.aligned.m16n8k16.row.col.f32.f16.f16.f32 "
                    "{%0,%1,%2,%3}, {%4,%5,%6,%7}, {%8,%9}, {%0,%1,%2,%3};"
                    : "+f"(acc[nt][0]), "+f"(acc[nt][1]),
                      "+f"(acc[nt][2]), "+f"(acc[nt][3])
                    : "r"(a0), "r"(a1), "r"(a2), "r"(a3),
                      "r"(wB[nt][ks].x), "r"(wB[nt][ks].y));
            }
        }

        // ---- 3. finish next-tile gather: A row (cache-hot) + fuse + STS ----
        {
            const float4* a4 = (const float4*)(A + (size_t)(validN ? dN : 0) * DIMV) + q * 4;
            uint4* hp = (uint4*)((char*)sHb + (p ^ 1) * (SHH_WORDS * 4)
                                 + e * (SHH * 4) + q * 32);
            if (q == 0) sDstb[(tn & 3) * 64 + e] = dN;
            #pragma unroll
            for (int v = 0; v < 2; v++) {
                float4 x0 = validN ? a4[2*v  ] : make_float4(0.f,0.f,0.f,0.f);
                float4 x1 = validN ? a4[2*v+1] : make_float4(0.f,0.f,0.f,0.f);
                uint4 hv;
                hv.x = pkh2(fmaxf(x0.x + bb[2*v].x, 0.f), fmaxf(x0.y + bb[2*v].y, 0.f));
                hv.y = pkh2(fmaxf(x0.z + bb[2*v].z, 0.f), fmaxf(x0.w + bb[2*v].w, 0.f));
                hv.z = pkh2(fmaxf(x1.x + bb[2*v+1].x, 0.f), fmaxf(x1.y + bb[2*v+1].y, 0.f));
                hv.w = pkh2(fmaxf(x1.z + bb[2*v+1].z, 0.f), fmaxf(x1.w + bb[2*v+1].w, 0.f));
                hp[v] = hv;
            }
        }

        // ---- 4. bias + write sMsg[p] ----
        float* msg = sMsgb + p * SMS_WORDS;
        #pragma unroll
        for (int nt = 0; nt < 4; nt++) {
            const int c2 = n0w + nt * 8 + 2 * qd;
            *(float2*)&msg[(m0 + grp    ) * SMS + c2] =
                make_float2(acc[nt][0] + bs0[nt], acc[nt][1] + bs1[nt]);
            *(float2*)&msg[(m0 + grp + 8) * SMS + c2] =
                make_float2(acc[nt][2] + bs0[nt], acc[nt][3] + bs1[nt]);
        }
        __syncthreads();   // the ONE barrier: sMsg[p], sH[p^1], sDst ready

        // ---- 5. scatter from sMsg[p] / sDst[t&3] ----
        {
            const int* sd = sDstb + (t & 3) * 64;
            int rd[16];
            #pragma unroll
            for (int i4 = 0; i4 < 4; i4++)
                *(int4*)&rd[i4 * 4] = *(const int4*)&sd[r2 + i4 * 4];
            float cur = msg[r2 * SMS + colS];
            #pragma unroll
            for (int i = 0; i < 16; i++) {
                const int de = rd[i];
                const bool last = (i == 15) || (rd[i + 1] != de);
                if (!last) {
                    cur = fmaxf(cur, msg[(r2 + i + 1) * SMS + colS]);
                } else {
                    if (de >= 0)
                        atomic_max_float(out + (size_t)de * DIMV + colS, cur);
                    if (i < 15)
                        cur = msg[(r2 + i + 1) * SMS + colS];
                }
            }
        }
        // no trailing barrier: next iter writes sMsg[p^1]/sH[p]/sDst[(t+2)&3],
        // none of which are read in this window (verified buffer rotation).
    }
}

extern "C" void kernel_launch(void* const* d_in, const int* in_sizes, int n_in,
                              void* d_out, int out_size)
{
    const float* x   = (const float*)d_in[0];
    const int*   ei  = (const int*)d_in[1];
    const float* W1a = (const float*)d_in[2];
    const float* b1a = (const float*)d_in[3];
    const float* W2a = (const float*)d_in[4];
    const float* b2a = (const float*)d_in[5];
    const float* W1b = (const float*)d_in[6];
    const float* b1b = (const float*)d_in[7];
    const float* W2b = (const float*)d_in[8];
    const float* b2b = (const float*)d_in[9];

    const int n_nodes = in_sizes[0] / DIMV;
    const int n_edges = in_sizes[1] / 2;
    const int* src = ei;
    const int* dst = ei + n_edges;

    float* out = (float*)d_out;
    float *h1, *Abuf, *Bbuf;
    cudaGetSymbolAddress((void**)&h1,   g_h1);
    cudaGetSymbolAddress((void**)&Abuf, g_A);
    cudaGetSymbolAddress((void**)&Bbuf, g_B);

    cudaFuncSetAttribute(pre_kernel,
                         cudaFuncAttributeMaxDynamicSharedMemorySize, PRE_SMEM_BYTES);
    cudaFuncSetAttribute(fused_spi_kernel,
                         cudaFuncAttributeMaxDynamicSharedMemorySize, PRE_SMEM_BYTES);
    cudaFuncSetAttribute(edge_kernel,
                         cudaFuncAttributeMaxDynamicSharedMemorySize, EDGE_SMEM_BYTES);

    const int n_feat = n_nodes * DIMV;
    const int init_blocks = (n_feat + TPB - 1) / TPB;
    const int pre_blocks  = (n_nodes + 63) / 64;
    const int edge_blocks = 148 * 2;
    const int eb = (n_edges + TPB - 1) / TPB;

    const int n_tiles = (n_edges + E_TILE - 1) / E_TILE;
    const int tiles_per_block = (n_tiles + edge_blocks - 1) / edge_blocks;

    // #1 histogram (g_count zeroed by previous scan / initial BSS)
    hist_kernel<<<eb, TPB>>>(dst, n_edges);
    // #2 exclusive scan + re-zero counts
    scan_zero_kernel<<<1, 1024>>>(n_nodes);
    // #3 fused: scatter-sort + init(h1) + pre(layer1)
    fused_spi_kernel<<<eb + init_blocks + pre_blocks, TPB, PRE_SMEM_BYTES>>>(
        src, dst, n_edges, x, W1a, b1a, Abuf, Bbuf, n_nodes,
        h1, n_feat, eb, init_blocks);
    // #4 edge layer 1  <-- ncu captures this launch
    edge_kernel<<<edge_blocks, TPB, EDGE_SMEM_BYTES>>>(Abuf, Bbuf, W2a, b2a,
                                                       h1, n_edges, tiles_per_block);

    // ---- layer 2 (h1 finalize fused via finite_fix) ----
    pre_kernel<<<pre_blocks, TPB, PRE_SMEM_BYTES>>>(h1, W1b, b1b, Abuf, Bbuf, n_nodes, 1);
    init_neg_inf_kernel<<<init_blocks, TPB>>>(out, n_feat);
    edge_kernel<<<edge_blocks, TPB, EDGE_SMEM_BYTES>>>(Abuf, Bbuf, W2b, b2b,
                                                       out, n_edges, tiles_per_block);
    finalize_kernel<<<init_blocks, TPB>>>(out, n_feat);
}

// round 13
// speedup vs baseline: 1.4244x; 1.1636x over previous
#include <cuda_runtime.h>
#include <cuda_fp16.h>
#include <cstdint>
#include <math.h>

// ----------------------------------------------------------------------------
// StackDevConv, factorized + dst-sorted edges + f16 mma + f16 A/B gather.
//   W1 = [Wa | Wb];  A[n] = x[n]@(Wa-Wb)^T + b1 ;  B[n] = x[n]@Wb^T
//     (computed fp32, stored f16)
//   per edge: h = relu(A[dst]+B[src]) in half2;  msg = h @ W2^T + b2 (f16 mma)
//   out[n] = segment_max(msg, dst) ; empty -> 0
// R12 ncu: still issue/latency-bound (L1 58%, issue 24%). Gather fp32 A/B was
// the largest remaining instruction+byte stream: f16 A/B halves gather LDGs
// and replaces 40 fp32 ALU+cvt with 16 half2 ops. Expected rel_err ~5e-4.
// ----------------------------------------------------------------------------

#define DIMV    64
#define TPB     256
#define PADW    68
#define E_TILE  64
#define MAX_NODES 50000
#define MAX_EDGES 800000

#define SHH 36                    // sH stride in 32-bit words (64 halves + pad)
#define SMS 72                    // sMsg stride (float)
#define SHH_WORDS (64*SHH)        // 2304
#define SMS_WORDS (64*SMS)        // 4608

__device__ float        g_h1[MAX_NODES * DIMV];
__device__ unsigned int g_A [MAX_NODES * 32];   // 64 halves/node
__device__ unsigned int g_B [MAX_NODES * 32];
__device__ int   g_count [MAX_NODES];
__device__ int   g_offset[MAX_NODES];
__device__ int   g_src_s[MAX_EDGES];
__device__ int   g_dst_s[MAX_EDGES];

#define PRE_SMEM_FLOATS (64*PADW*3 + 64)
#define PRE_SMEM_BYTES  (PRE_SMEM_FLOATS*4)

// edge smem: sH[2 x 2304] + sMsg[2 x 4608] + sDst[4][64]
#define EDGE_SMEM_WORDS (2*SHH_WORDS + 2*SMS_WORDS + 4*64)
#define EDGE_SMEM_BYTES (EDGE_SMEM_WORDS*4)

__device__ __forceinline__ void atomic_max_float(float* addr, float value) {
    unsigned int ui = __float_as_uint(value);
    if ((int)ui >= 0) atomicMax((int*)addr, (int)ui);
    else              atomicMin((unsigned int*)addr, ui);
}

__device__ __forceinline__ unsigned int pkh2(float lo, float hi) {
    __half2 h = __float22half2_rn(make_float2(lo, hi));
    return *reinterpret_cast<unsigned int*>(&h);
}

// relu(a+b) in half2, packed words
__device__ __forceinline__ unsigned int haddrelu2(unsigned int a, unsigned int b) {
    __half2 r = __hmax2(__hadd2(*reinterpret_cast<__half2*>(&a),
                                *reinterpret_cast<__half2*>(&b)),
                        __half2(__half(0.0f), __half(0.0f)));
    return *reinterpret_cast<unsigned int*>(&r);
}

__device__ __forceinline__ void ldsm_x4(unsigned &r0, unsigned &r1,
                                        unsigned &r2, unsigned &r3,
                                        unsigned addr) {
    asm volatile("ldmatrix.sync.aligned.m8n8.x4.shared.b16 {%0,%1,%2,%3}, [%4];"
                 : "=r"(r0), "=r"(r1), "=r"(r2), "=r"(r3) : "r"(addr));
}

__global__ void finalize_kernel(float* p, int n) {
    int i = blockIdx.x * blockDim.x + threadIdx.x;
    if (i < n) { float v = p[i]; if (!isfinite(v)) p[i] = 0.0f; }
}

// ---------------- counting sort by dst ----------------
__global__ void hist_kernel(const int* __restrict__ dst, int n_edges) {
    int i = blockIdx.x * blockDim.x + threadIdx.x;
    if (i < n_edges) atomicAdd(&g_count[dst[i]], 1);
}

__global__ void scan_zero_kernel(int n_nodes) {
    __shared__ int partial[1024];
    const int tid = threadIdx.x;
    const int chunk = (n_nodes + 1023) / 1024;
    const int begin = tid * chunk;
    const int end   = min(begin + chunk, n_nodes);
    int s = 0;
    for (int i = begin; i < end; i++) s += g_count[i];
    partial[tid] = s;
    __syncthreads();
    for (int off = 1; off < 1024; off <<= 1) {
        int v = partial[tid];
        int add = (tid >= off) ? partial[tid - off] : 0;
        __syncthreads();
        partial[tid] = v + add;
        __syncthreads();
    }
    int base = (tid > 0) ? partial[tid - 1] : 0;
    for (int i = begin; i < end; i++) {
        g_offset[i] = base;
        base += g_count[i];
        g_count[i] = 0;
    }
}

// ---------------- per-node precompute body (fp32 math, f16 store) ----------------
__device__ __forceinline__
void pre_body(float* smem, int n0,
              const float* __restrict__ x,
              const float* __restrict__ W1, const float* __restrict__ b1,
              unsigned int* __restrict__ Ah, unsigned int* __restrict__ Bh,
              int n_nodes, int finite_fix, int tid)
{
    float* sWdT = smem;
    float* sWbT = sWdT + 64 * PADW;
    float* sB1  = sWbT + 64 * PADW;
    float* sXT  = sB1 + 64;

    for (int i = tid; i < 64 * 64; i += TPB) {
        int c = i >> 6, k = i & 63;
        float wa = W1[c * 128 + k];
        float wb = W1[c * 128 + 64 + k];
        sWdT[k * PADW + c] = wa - wb;
        sWbT[k * PADW + c] = wb;
    }
    if (tid < 64) sB1[tid] = b1[tid];

    {
        const int e = tid >> 2;
        const int q = tid & 3;
        const int node = n0 + e;
        const float4* xr = (const float4*)(x + (size_t)(node < n_nodes ? node : 0) * DIMV);
        #pragma unroll
        for (int v = 0; v < 4; v++) {
            const int c4 = q * 4 + v;
            float4 a = (node < n_nodes) ? xr[c4] : make_float4(0.f,0.f,0.f,0.f);
            if (finite_fix) {
                if (!isfinite(a.x)) a.x = 0.f;
                if (!isfinite(a.y)) a.y = 0.f;
                if (!isfinite(a.z)) a.z = 0.f;
                if (!isfinite(a.w)) a.w = 0.f;
            }
            const int c = c4 * 4;
            sXT[(c + 0) * PADW + e] = a.x;
            sXT[(c + 1) * PADW + e] = a.y;
            sXT[(c + 2) * PADW + e] = a.z;
            sXT[(c + 3) * PADW + e] = a.w;
        }
    }
    __syncthreads();

    const int ty = tid >> 4, tx = tid & 15;
    const int r = ty * 4, cc = tx * 4;

    float accA[4][4], accB[4][4];
    #pragma unroll
    for (int i = 0; i < 4; i++)
        #pragma unroll
        for (int j = 0; j < 4; j++) { accA[i][j] = sB1[cc + j]; accB[i][j] = 0.f; }

    #pragma unroll 2
    for (int k = 0; k < 64; k++) {
        const float4 xf = *(const float4*)&sXT[k * PADW + r];
        const float4 wd = *(const float4*)&sWdT[k * PADW + cc];
        const float4 wb = *(const float4*)&sWbT[k * PADW + cc];
        const float a0 = xf.x, a1 = xf.y, a2 = xf.z, a3 = xf.w;
        accA[0][0]+=a0*wd.x; accA[0][1]+=a0*wd.y; accA[0][2]+=a0*wd.z; accA[0][3]+=a0*wd.w;
        accA[1][0]+=a1*wd.x; accA[1][1]+=a1*wd.y; accA[1][2]+=a1*wd.z; accA[1][3]+=a1*wd.w;
        accA[2][0]+=a2*wd.x; accA[2][1]+=a2*wd.y; accA[2][2]+=a2*wd.z; accA[2][3]+=a2*wd.w;
        accA[3][0]+=a3*wd.x; accA[3][1]+=a3*wd.y; accA[3][2]+=a3*wd.z; accA[3][3]+=a3*wd.w;
        accB[0][0]+=a0*wb.x; accB[0][1]+=a0*wb.y; accB[0][2]+=a0*wb.z; accB[0][3]+=a0*wb.w;
        accB[1][0]+=a1*wb.x; accB[1][1]+=a1*wb.y; accB[1][2]+=a1*wb.z; accB[1][3]+=a1*wb.w;
        accB[2][0]+=a2*wb.x; accB[2][1]+=a2*wb.y; accB[2][2]+=a2*wb.z; accB[2][3]+=a2*wb.w;
        accB[3][0]+=a3*wb.x; accB[3][1]+=a3*wb.y; accB[3][2]+=a3*wb.z; accB[3][3]+=a3*wb.w;
    }

    #pragma unroll
    for (int i = 0; i < 4; i++) {
        const int node = n0 + r + i;
        if (node < n_nodes) {
            *(uint2*)&Ah[(size_t)node * 32 + (cc >> 1)] =
                make_uint2(pkh2(accA[i][0], accA[i][1]), pkh2(accA[i][2], accA[i][3]));
            *(uint2*)&Bh[(size_t)node * 32 + (cc >> 1)] =
                make_uint2(pkh2(accB[i][0], accB[i][1]), pkh2(accB[i][2], accB[i][3]));
        }
    }
}

// ---------------- fused scatter + init + pre (block-range dispatch) ----------------
// nblk_scatter=0 reuses this for layer 2 (pre + init only).
__global__ __launch_bounds__(TPB, 3)
void fused_spi_kernel(const int* __restrict__ src, const int* __restrict__ dst,
                      int n_edges,
                      const float* __restrict__ x,
                      const float* __restrict__ W1, const float* __restrict__ b1,
                      unsigned int* __restrict__ Ah, unsigned int* __restrict__ Bh,
                      int n_nodes,
                      float* __restrict__ init_buf, int n_feat,
                      int nblk_scatter, int nblk_init, int finite_fix)
{
    extern __shared__ float fsm[];
    const int b = blockIdx.x;
    if (b < nblk_scatter) {
        int i = b * TPB + threadIdx.x;
        if (i < n_edges) {
            int d = dst[i];
            int pos = atomicAdd(&g_offset[d], 1);
            g_src_s[pos] = src[i];
            g_dst_s[pos] = d;
        }
    } else if (b < nblk_scatter + nblk_init) {
        int i = (b - nblk_scatter) * TPB + threadIdx.x;
        if (i < n_feat) ((unsigned int*)init_buf)[i] = 0xFF800000u;
    } else {
        pre_body(fsm, (b - nblk_scatter - nblk_init) * 64,
                 x, W1, b1, Ah, Bh, n_nodes, finite_fix, threadIdx.x);
    }
}

// ---------------- edge kernel: f16 mma + f16 gather, 1 barrier/tile ----------------
__global__ __launch_bounds__(TPB, 2)
void edge_kernel(const unsigned int* __restrict__ Ah,
                 const unsigned int* __restrict__ Bh,
                 const float* __restrict__ W2, const float* __restrict__ b2,
                 float* __restrict__ out, int n_edges, int tiles_per_block)
{
    extern __shared__ unsigned int usmem[];
    unsigned int* sHb   = usmem;                               // 2 x [64][SHH]
    float*        sMsgb = (float*)(usmem + 2 * SHH_WORDS);     // 2 x [64][SMS]
    int*          sDstb = (int*)(usmem + 2 * SHH_WORDS + 2 * SMS_WORDS); // 4 x [64]

    const int tid  = threadIdx.x;
    const int wid  = tid >> 5;
    const int lane = tid & 31;
    const int grp  = lane >> 2;
    const int qd   = lane & 3;

    const int m0  = (wid >> 1) * 16;   // warp's edge-group base
    const int n0w = (wid & 1) * 32;    // warp's column half

    // ---- W2 f16 fragments -> registers, ONCE (m16n8k16 B layout) ----
    uint2 wB[4][4];
    #pragma unroll
    for (int nt = 0; nt < 4; nt++) {
        const int row = n0w + nt * 8 + grp;
        #pragma unroll
        for (int ks = 0; ks < 4; ks++) {
            const int k0 = ks * 16 + 2 * qd;
            wB[nt][ks] = make_uint2(
                pkh2(W2[row * 64 + k0    ], W2[row * 64 + k0 + 1]),
                pkh2(W2[row * 64 + k0 + 8], W2[row * 64 + k0 + 9]));
        }
    }
    float bs0[4], bs1[4];
    #pragma unroll
    for (int nt = 0; nt < 4; nt++) {
        const int col = n0w + nt * 8 + 2 * qd;
        bs0[nt] = b2[col];
        bs1[nt] = b2[col + 1];
    }

    const int e = tid >> 2, q = tid & 3;        // gather role: 4 threads/edge
    const int colS = tid & 63, r2 = (tid >> 6) * 16;   // scatter role

    const int n_tiles = (n_edges + E_TILE - 1) / E_TILE;
    const int t0 = blockIdx.x * tiles_per_block;
    const int t1 = min(t0 + tiles_per_block, n_tiles);
    if (t0 >= t1) return;   // block-uniform

    unsigned int sbase;
    asm("{ .reg .u64 t; cvta.to.shared.u64 t, %1; cvt.u32.u64 %0, t; }"
        : "=r"(sbase) : "l"((void*)usmem));
    const unsigned int lds_off =
        ((unsigned)((m0 + (lane & 15)) * SHH + (lane >> 4) * 4)) * 4u;

    // ---- prologue: full gather of tile t0 -> sH buf0, sDst[t0&3] ----
    {
        const int eg = t0 * E_TILE + e;
        const bool valid = (eg < n_edges);
        int s = 0, d = -1;
        if (valid) { s = g_src_s[eg]; d = g_dst_s[eg]; }
        const uint4* a4 = (const uint4*)(Ah + (size_t)(valid ? d : 0) * 32) + q * 2;
        const uint4* b4 = (const uint4*)(Bh + (size_t)s * 32) + q * 2;
        uint4* hp = (uint4*)((char*)sHb + e * (SHH * 4) + q * 32);
        if (q == 0) sDstb[(t0 & 3) * 64 + e] = d;
        #pragma unroll
        for (int v = 0; v < 2; v++) {
            uint4 a = valid ? a4[v] : make_uint4(0,0,0,0);
            uint4 b = valid ? b4[v] : make_uint4(0,0,0,0);
            uint4 hv;
            hv.x = haddrelu2(a.x, b.x);
            hv.y = haddrelu2(a.y, b.y);
            hv.z = haddrelu2(a.z, b.z);
            hv.w = haddrelu2(a.w, b.w);
            hp[v] = hv;
        }
    }
    __syncthreads();

    int p = 0;
    for (int t = t0; t < t1; t++, p ^= 1) {
        // ---- 1. prefetch next tile's random B[src] (issues before mma) ----
        const int tn = t + 1;
        const int egN = tn * E_TILE + e;
        const bool validN = (tn < t1) && (egN < n_edges);
        int sN = 0, dN = -1;
        if (validN) { sN = g_src_s[egN]; dN = g_dst_s[egN]; }
        uint4 bb[2];
        {
            const uint4* b4 = (const uint4*)(Bh + (size_t)sN * 32) + q * 2;
            #pragma unroll
            for (int v = 0; v < 2; v++)
                bb[v] = validN ? b4[v] : make_uint4(0,0,0,0);
        }

        // ---- 2. f16 mma from sH[p] via ldmatrix, W2 frags in regs ----
        float acc[4][4];
        #pragma unroll
        for (int nt = 0; nt < 4; nt++)
            #pragma unroll
            for (int j = 0; j < 4; j++) acc[nt][j] = 0.f;

        const unsigned int abase = sbase + (unsigned)p * (SHH_WORDS * 4u) + lds_off;
        #pragma unroll
        for (int ks = 0; ks < 4; ks++) {
            unsigned int a0, a1, a2, a3;
            ldsm_x4(a0, a1, a2, a3, abase + ks * 32u);
            #pragma unroll
            for (int nt = 0; nt < 4; nt++) {
                asm volatile(
                    "mma.sync.aligned.m16n8k16.row.col.f32.f16.f16.f32 "
                    "{%0,%1,%2,%3}, {%4,%5,%6,%7}, {%8,%9}, {%0,%1,%2,%3};"
                    : "+f"(acc[nt][0]), "+f"(acc[nt][1]),
                      "+f"(acc[nt][2]), "+f"(acc[nt][3])
                    : "r"(a0), "r"(a1), "r"(a2), "r"(a3),
                      "r"(wB[nt][ks].x), "r"(wB[nt][ks].y));
            }
        }

        // ---- 3. finish next-tile gather: A row (cache-hot) + fuse + STS ----
        {
            const uint4* a4 = (const uint4*)(Ah + (size_t)(validN ? dN : 0) * 32) + q * 2;
            uint4* hp = (uint4*)((char*)sHb + (p ^ 1) * (SHH_WORDS * 4)
                                 + e * (SHH * 4) + q * 32);
            if (q == 0) sDstb[(tn & 3) * 64 + e] = dN;
            #pragma unroll
            for (int v = 0; v < 2; v++) {
                uint4 a = validN ? a4[v] : make_uint4(0,0,0,0);
                uint4 hv;
                hv.x = haddrelu2(a.x, bb[v].x);
                hv.y = haddrelu2(a.y, bb[v].y);
                hv.z = haddrelu2(a.z, bb[v].z);
                hv.w = haddrelu2(a.w, bb[v].w);
                hp[v] = hv;
            }
        }

        // ---- 4. bias + write sMsg[p] ----
        float* msg = sMsgb + p * SMS_WORDS;
        #pragma unroll
        for (int nt = 0; nt < 4; nt++) {
            const int c2 = n0w + nt * 8 + 2 * qd;
            *(float2*)&msg[(m0 + grp    ) * SMS + c2] =
                make_float2(acc[nt][0] + bs0[nt], acc[nt][1] + bs1[nt]);
            *(float2*)&msg[(m0 + grp + 8) * SMS + c2] =
                make_float2(acc[nt][2] + bs0[nt], acc[nt][3] + bs1[nt]);
        }
        __syncthreads();   // the ONE barrier: sMsg[p], sH[p^1], sDst ready

        // ---- 5. scatter from sMsg[p] / sDst[t&3] ----
        {
            const int* sd = sDstb + (t & 3) * 64;
            int rd[16];
            #pragma unroll
            for (int i4 = 0; i4 < 4; i4++)
                *(int4*)&rd[i4 * 4] = *(const int4*)&sd[r2 + i4 * 4];
            float cur = msg[r2 * SMS + colS];
            #pragma unroll
            for (int i = 0; i < 16; i++) {
                const int de = rd[i];
                const bool last = (i == 15) || (rd[i + 1] != de);
                if (!last) {
                    cur = fmaxf(cur, msg[(r2 + i + 1) * SMS + colS]);
                } else {
                    if (de >= 0)
                        atomic_max_float(out + (size_t)de * DIMV + colS, cur);
                    if (i < 15)
                        cur = msg[(r2 + i + 1) * SMS + colS];
                }
            }
        }
        // no trailing barrier (verified buffer rotation).
    }
}

extern "C" void kernel_launch(void* const* d_in, const int* in_sizes, int n_in,
                              void* d_out, int out_size)
{
    const float* x   = (const float*)d_in[0];
    const int*   ei  = (const int*)d_in[1];
    const float* W1a = (const float*)d_in[2];
    const float* b1a = (const float*)d_in[3];
    const float* W2a = (const float*)d_in[4];
    const float* b2a = (const float*)d_in[5];
    const float* W1b = (const float*)d_in[6];
    const float* b1b = (const float*)d_in[7];
    const float* W2b = (const float*)d_in[8];
    const float* b2b = (const float*)d_in[9];

    const int n_nodes = in_sizes[0] / DIMV;
    const int n_edges = in_sizes[1] / 2;
    const int* src = ei;
    const int* dst = ei + n_edges;

    float* out = (float*)d_out;
    float* h1;
    unsigned int *Abuf, *Bbuf;
    cudaGetSymbolAddress((void**)&h1,   g_h1);
    cudaGetSymbolAddress((void**)&Abuf, g_A);
    cudaGetSymbolAddress((void**)&Bbuf, g_B);

    cudaFuncSetAttribute(fused_spi_kernel,
                         cudaFuncAttributeMaxDynamicSharedMemorySize, PRE_SMEM_BYTES);
    cudaFuncSetAttribute(edge_kernel,
                         cudaFuncAttributeMaxDynamicSharedMemorySize, EDGE_SMEM_BYTES);

    const int n_feat = n_nodes * DIMV;
    const int init_blocks = (n_feat + TPB - 1) / TPB;
    const int pre_blocks  = (n_nodes + 63) / 64;
    const int edge_blocks = 148 * 2;
    const int eb = (n_edges + TPB - 1) / TPB;

    const int n_tiles = (n_edges + E_TILE - 1) / E_TILE;
    const int tiles_per_block = (n_tiles + edge_blocks - 1) / edge_blocks;

    // #1 histogram (g_count zeroed by previous scan / initial BSS)
    hist_kernel<<<eb, TPB>>>(dst, n_edges);
    // #2 exclusive scan + re-zero counts
    scan_zero_kernel<<<1, 1024>>>(n_nodes);
    // #3 fused: scatter-sort + init(h1) + pre(layer1)
    fused_spi_kernel<<<eb + init_blocks + pre_blocks, TPB, PRE_SMEM_BYTES>>>(
        src, dst, n_edges, x, W1a, b1a, Abuf, Bbuf, n_nodes,
        h1, n_feat, eb, init_blocks, 0);
    // #4 edge layer 1  <-- ncu captures this launch
    edge_kernel<<<edge_blocks, TPB, EDGE_SMEM_BYTES>>>(Abuf, Bbuf, W2a, b2a,
                                                       h1, n_edges, tiles_per_block);
    // #5 fused: init(out) + pre(layer2, finite_fix on h1)
    fused_spi_kernel<<<init_blocks + pre_blocks, TPB, PRE_SMEM_BYTES>>>(
        src, dst, n_edges, h1, W1b, b1b, Abuf, Bbuf, n_nodes,
        out, n_feat, 0, init_blocks, 1);
    // #6 edge layer 2
    edge_kernel<<<edge_blocks, TPB, EDGE_SMEM_BYTES>>>(Abuf, Bbuf, W2b, b2b,
                                                       out, n_edges, tiles_per_block);
    // #7 finalize empty segments
    finalize_kernel<<<init_blocks, TPB>>>(out, n_feat);
}